// round 2
// baseline (speedup 1.0000x reference)
#include <cuda_runtime.h>
#include <cstdint>

#define D 200
#define NREL 474
#define NTAB 948        // 2*NREL
#define VMAX 100000
#define EMAX 1000000
#define GR 32           // gemm rows per tile
#define NVB 200         // agg vertex-blocks per chunk
#define PER_B 500       // VMAX / NVB

// ---- scratch (__device__ globals; no cudaMalloc allowed) ----
__device__ __align__(16) float g_Mtab[NTAB * D];   // softmax(rel@W)/3 tables
__device__ __align__(16) float g_Weff[D * D];      // (circulant(loop_rel) @ loop_w)/3
__device__ __align__(16) float2 g_sedge[EMAX];     // sorted (row_as_int, norm)
__device__ int g_cnt[VMAX];
__device__ int g_off[VMAX + 1];
__device__ int g_cursor[VMAX];
__device__ int g_bsum[512];
__device__ int g_boff[512];
__device__ float g_sum[D];
__device__ float g_sumsq[D];
__device__ float g_scale[D];
__device__ float g_shift[D];

// ---- packed f32x2 helpers ----
__device__ __forceinline__ unsigned long long fma2(unsigned long long a,
                                                   unsigned long long b,
                                                   unsigned long long c) {
    unsigned long long d;
    asm("fma.rn.f32x2 %0, %1, %2, %3;" : "=l"(d) : "l"(a), "l"(b), "l"(c));
    return d;
}
__device__ __forceinline__ unsigned long long pack2(float lo, float hi) {
    unsigned long long d;
    asm("mov.b64 %0, {%1, %2};" : "=l"(d) : "f"(lo), "f"(hi));
    return d;
}
__device__ __forceinline__ void unpack2(unsigned long long v, float& lo, float& hi) {
    asm("mov.b64 {%0, %1}, %2;" : "=f"(lo), "=f"(hi) : "l"(v));
}
// 16B XOR swizzle on byte offsets: makes lane-strided float4 smem reads conflict-free
__device__ __forceinline__ int sw16(int a) { return a ^ ((a >> 3) & 16); }

// ============================================================================
// zero: counts + BN accumulators
// ============================================================================
__global__ void zero_kernel(int V) {
    int i = blockIdx.x * 256 + threadIdx.x;
    if (i < V) g_cnt[i] = 0;
    if (i < D) { g_sum[i] = 0.f; g_sumsq[i] = 0.f; }
}

// ============================================================================
// histogram of dst
// ============================================================================
__global__ void hist_kernel(const int* __restrict__ dst, int E) {
    int e = blockIdx.x * 256 + threadIdx.x;
    if (e < E) atomicAdd(&g_cnt[dst[e]], 1);
}

// ============================================================================
// 2-level exclusive scan of g_cnt -> g_off (+ cursor copy)
// ============================================================================
__global__ void scan1_kernel(int V) {
    __shared__ int sm[256];
    int t = threadIdx.x, i = blockIdx.x * 256 + t;
    sm[t] = (i < V) ? g_cnt[i] : 0;
    __syncthreads();
    for (int s = 128; s > 0; s >>= 1) {
        if (t < s) sm[t] += sm[t + s];
        __syncthreads();
    }
    if (t == 0) g_bsum[blockIdx.x] = sm[0];
}
__global__ void scan2_kernel(int NB) {
    __shared__ int sm[512];
    int t = threadIdx.x;
    int v0 = (t < NB) ? g_bsum[t] : 0;
    sm[t] = v0;
    __syncthreads();
    for (int s = 1; s < 512; s <<= 1) {
        int u = (t >= s) ? sm[t - s] : 0;
        __syncthreads();
        sm[t] += u;
        __syncthreads();
    }
    if (t < NB) g_boff[t] = sm[t] - v0;   // exclusive
}
__global__ void scan3_kernel(int V, int E) {
    __shared__ int sm[256];
    int b = blockIdx.x, t = threadIdx.x, i = b * 256 + t;
    int c = (i < V) ? g_cnt[i] : 0;
    sm[t] = c;
    __syncthreads();
    for (int s = 1; s < 256; s <<= 1) {
        int u = (t >= s) ? sm[t - s] : 0;
        __syncthreads();
        sm[t] += u;
        __syncthreads();
    }
    int excl = sm[t] - c + g_boff[b];
    if (i < V) { g_off[i] = excl; g_cursor[i] = excl; }
    if (i == V - 1) g_off[V] = E;
}

// ============================================================================
// permute edges into CSR order; payload = (table_row, norm)
// ============================================================================
__global__ void sortscatter_kernel(const int* __restrict__ edge_type,
                                   const int* __restrict__ dst,
                                   const float* __restrict__ edge_norm,
                                   int E, int half) {
    int e = blockIdx.x * 256 + threadIdx.x;
    if (e >= E) return;
    int v = dst[e];
    int row = edge_type[e] + ((e >= half) ? NREL : 0);
    int pos = atomicAdd(&g_cursor[v], 1);
    g_sedge[pos] = make_float2(__int_as_float(row), edge_norm[e]);
}

// ============================================================================
// prep: g_Mtab (948 softmaxed msg rows /3), g_Weff, rel_out = rel_repr @ w_rel
// ============================================================================
__global__ void prep_kernel(const float* __restrict__ rel_repr,
                            const float* __restrict__ in_w,
                            const float* __restrict__ out_w,
                            const float* __restrict__ loop_w,
                            const float* __restrict__ w_rel,
                            const float* __restrict__ loop_rel,
                            float* __restrict__ rel_out) {
    __shared__ float rs[D];
    __shared__ float red[256];
    int b = blockIdx.x, tid = threadIdx.x;

    if (b < NTAB) {
        int t = (b < NREL) ? b : b - NREL;
        const float* W = (b < NREL) ? in_w : out_w;
        if (tid < D) rs[tid] = rel_repr[t * D + tid];
        __syncthreads();
        float acc = 0.f;
        if (tid < D) {
            #pragma unroll 4
            for (int k = 0; k < D; k++) acc = fmaf(rs[k], W[k * D + tid], acc);
        }
        red[tid] = (tid < D) ? acc : -1e30f;
        __syncthreads();
        for (int s = 128; s > 0; s >>= 1) {
            if (tid < s) red[tid] = fmaxf(red[tid], red[tid + s]);
            __syncthreads();
        }
        float mx = red[0];
        __syncthreads();
        float e = (tid < D) ? expf(acc - mx) : 0.f;
        red[tid] = e;
        __syncthreads();
        for (int s = 128; s > 0; s >>= 1) {
            if (tid < s) red[tid] += red[tid + s];
            __syncthreads();
        }
        float inv = 1.f / (red[0] * 3.f);
        if (tid < D) g_Mtab[b * D + tid] = e * inv;
    } else if (b < NTAB + D) {
        int kk = b - NTAB;
        if (tid < D) rs[tid] = loop_rel[tid];
        __syncthreads();
        if (tid < D) {
            float acc = 0.f;
            #pragma unroll 4
            for (int m = 0; m < D; m++) {
                int mm = m + kk; if (mm >= D) mm -= D;
                acc = fmaf(rs[mm], loop_w[m * D + tid], acc);
            }
            g_Weff[kk * D + tid] = acc * (1.f / 3.f);
        }
    } else {
        int t = b - (NTAB + D);
        if (tid < D) rs[tid] = rel_repr[t * D + tid];
        __syncthreads();
        if (tid < D) {
            float acc = 0.f;
            #pragma unroll 4
            for (int k = 0; k < D; k++) acc = fmaf(rs[k], w_rel[k * D + tid], acc);
            rel_out[t * D + tid] = acc;
        }
    }
}

// ============================================================================
// persistent GEMM: out = x @ Weff + bias. Weff in smem (swizzled), loaded once
// per CTA; loop over 32-row tiles. Thread tile 4 rows x 8 cols, FFMA2.
// ============================================================================
__global__ void __launch_bounds__(256, 1)
gemm_kernel(const float* __restrict__ x,
            const float* __restrict__ bias,
            float* __restrict__ out, int V) {
    extern __shared__ float sm[];
    float* Ws = sm;                 // D*D (swizzled)
    float* xs = sm + D * D;         // GR*D
    int tid = threadIdx.x;
    char* Wb = reinterpret_cast<char*>(Ws);
    for (int i = tid; i < D * D; i += 256)
        *reinterpret_cast<float*>(Wb + sw16(i * 4)) = g_Weff[i];

    int team = tid >> 5;            // 8 teams (warps), 4 rows each
    int cg = tid & 31;              // 25 active colgroups of 8
    int j0 = cg * 8;
    float b0[8];
    if (cg < 25) {
        #pragma unroll
        for (int c = 0; c < 8; c++) b0[c] = bias[j0 + c];
    }

    int ntiles = V / GR;
    for (int tile = blockIdx.x; tile < ntiles; tile += gridDim.x) {
        int row0 = tile * GR;
        __syncthreads();
        for (int i = tid; i < GR * D; i += 256) xs[i] = x[(size_t)row0 * D + i];
        __syncthreads();
        if (cg >= 25) continue;

        unsigned long long a[16];
        #pragma unroll
        for (int i = 0; i < 16; i++) a[i] = 0ull;
        const float* xrow = xs + team * 4 * D;
        #pragma unroll 2
        for (int k = 0; k < D; k++) {
            int base = (k * D + j0) * 4;
            float4 wa = *reinterpret_cast<const float4*>(Wb + sw16(base));
            float4 wb = *reinterpret_cast<const float4*>(Wb + sw16(base + 16));
            unsigned long long w0 = pack2(wa.x, wa.y);
            unsigned long long w1 = pack2(wa.z, wa.w);
            unsigned long long w2 = pack2(wb.x, wb.y);
            unsigned long long w3 = pack2(wb.z, wb.w);
            #pragma unroll
            for (int r = 0; r < 4; r++) {
                float xv = xrow[r * D + k];
                unsigned long long xx = pack2(xv, xv);
                a[r * 4 + 0] = fma2(xx, w0, a[r * 4 + 0]);
                a[r * 4 + 1] = fma2(xx, w1, a[r * 4 + 1]);
                a[r * 4 + 2] = fma2(xx, w2, a[r * 4 + 2]);
                a[r * 4 + 3] = fma2(xx, w3, a[r * 4 + 3]);
            }
        }
        #pragma unroll
        for (int r = 0; r < 4; r++) {
            float v[8];
            unpack2(a[r * 4 + 0], v[0], v[1]);
            unpack2(a[r * 4 + 1], v[2], v[3]);
            unpack2(a[r * 4 + 2], v[4], v[5]);
            unpack2(a[r * 4 + 3], v[6], v[7]);
            float* op = out + (size_t)(row0 + team * 4 + r) * D + j0;
            float4 o0 = make_float4(v[0] + b0[0], v[1] + b0[1], v[2] + b0[2], v[3] + b0[3]);
            float4 o1 = make_float4(v[4] + b0[4], v[5] + b0[5], v[6] + b0[6], v[7] + b0[7]);
            *reinterpret_cast<float4*>(op) = o0;
            *reinterpret_cast<float4*>(op + 4) = o1;
        }
    }
}

// ============================================================================
// agg: CSR gather. grid = (NVB, 4 column-chunks). 948x50 table chunk in smem.
// 4 groups of 64 threads (50 active); out += agg; BN stats fused.
// ============================================================================
__global__ void __launch_bounds__(256, 1)
agg_kernel(float* __restrict__ out) {
    extern __shared__ float tab[];       // 948*50
    int chunk = blockIdx.y;
    int c0 = chunk * 50;
    int tid = threadIdx.x;
    for (int i = tid; i < NTAB * 50; i += 256)
        tab[i] = g_Mtab[(i / 50) * D + c0 + (i % 50)];
    __syncthreads();

    int g = tid >> 6;                    // 4 groups
    int j = tid & 63;                    // 50 active lanes per group
    if (j >= 50) return;
    int vstart = blockIdx.x * PER_B;
    float s = 0.f, q = 0.f;
    for (int v = vstart + g; v < vstart + PER_B; v += 4) {
        int e0 = g_off[v], e1 = g_off[v + 1];
        float acc = 0.f;
        for (int e = e0; e < e1; e++) {
            float2 ed = g_sedge[e];
            int row = __float_as_int(ed.x);
            acc = fmaf(ed.y, tab[row * 50 + j], acc);
        }
        size_t idx = (size_t)v * D + c0 + j;
        float val = out[idx] + acc;
        out[idx] = val;
        s += val;
        q += val * val;
    }
    atomicAdd(&g_sum[c0 + j], s);
    atomicAdd(&g_sumsq[c0 + j], q);
}

// ============================================================================
// BN params + final normalize
// ============================================================================
__global__ void bn_params_kernel(const float* __restrict__ bn_w,
                                 const float* __restrict__ bn_b, float invV) {
    int j = threadIdx.x;
    if (j < D) {
        float mean = g_sum[j] * invV;
        float var = g_sumsq[j] * invV - mean * mean;
        float sc = bn_w[j] * rsqrtf(var + 1e-5f);
        g_scale[j] = sc;
        g_shift[j] = bn_b[j] - mean * sc;
    }
}

__global__ void bn_final_kernel(float* __restrict__ out, int total4) {
    int i = blockIdx.x * 256 + threadIdx.x;
    if (i >= total4) return;
    int c0 = (i % 50) * 4;
    float4 v = reinterpret_cast<float4*>(out)[i];
    v.x = v.x * g_scale[c0]     + g_shift[c0];
    v.y = v.y * g_scale[c0 + 1] + g_shift[c0 + 1];
    v.z = v.z * g_scale[c0 + 2] + g_shift[c0 + 2];
    v.w = v.w * g_scale[c0 + 3] + g_shift[c0 + 3];
    reinterpret_cast<float4*>(out)[i] = v;
}

// ============================================================================
extern "C" void kernel_launch(void* const* d_in, const int* in_sizes, int n_in,
                              void* d_out, int out_size) {
    const float* x         = (const float*)d_in[0];
    const float* rel_repr  = (const float*)d_in[1];
    const float* edge_norm = (const float*)d_in[2];
    const float* in_w      = (const float*)d_in[3];
    const float* out_w     = (const float*)d_in[4];
    const float* loop_w    = (const float*)d_in[5];
    const float* w_rel     = (const float*)d_in[6];
    const float* loop_rel  = (const float*)d_in[7];
    const float* bias      = (const float*)d_in[8];
    const float* bn_w      = (const float*)d_in[9];
    const float* bn_b      = (const float*)d_in[10];
    const int*   edge_type = (const int*)d_in[11];
    const int*   dst       = (const int*)d_in[12];
    float* out = (float*)d_out;

    int V = in_sizes[0] / D;           // 100000
    int E = in_sizes[2];               // 1000000
    float* rel_out = out + (size_t)V * D;
    int NB = (V + 255) / 256;          // 391

    size_t smem_gemm = (size_t)(D * D + GR * D) * sizeof(float);    // 185.6 KB
    size_t smem_agg  = (size_t)(NTAB * 50) * sizeof(float);         // 189.6 KB
    cudaFuncSetAttribute(gemm_kernel,
                         cudaFuncAttributeMaxDynamicSharedMemorySize, (int)smem_gemm);
    cudaFuncSetAttribute(agg_kernel,
                         cudaFuncAttributeMaxDynamicSharedMemorySize, (int)smem_agg);

    // edge sort (CSR) pipeline
    zero_kernel<<<NB, 256>>>(V);
    hist_kernel<<<(E + 255) / 256, 256>>>(dst, E);
    scan1_kernel<<<NB, 256>>>(V);
    scan2_kernel<<<1, 512>>>(NB);
    scan3_kernel<<<NB, 256>>>(V, E);
    sortscatter_kernel<<<(E + 255) / 256, 256>>>(edge_type, dst, edge_norm, E, E / 2);

    // tables + Weff + rel_out
    prep_kernel<<<NTAB + D + NREL, 256>>>(rel_repr, in_w, out_w, loop_w,
                                          w_rel, loop_rel, rel_out);
    // self-loop GEMM: out = x @ Weff + bias
    gemm_kernel<<<148, 256, smem_gemm>>>(x, bias, out, V);
    // CSR gather of edge messages + fused BN stats
    agg_kernel<<<dim3(NVB, 4), 256, smem_agg>>>(out);
    // batchnorm
    bn_params_kernel<<<1, 256>>>(bn_w, bn_b, 1.f / (float)V);
    int total4 = V * (D / 4);
    bn_final_kernel<<<(total4 + 255) / 256, 256>>>(out, total4);
}

// round 3
// speedup vs baseline: 2.8436x; 2.8436x over previous
#include <cuda_runtime.h>
#include <cstdint>

#define D 200
#define NREL 474
#define NTAB 948        // 2*NREL
#define VMAX 100000
#define EMAX 1000000
#define GR 32           // rows per tile (8 warps x 4 rows)

// ---- scratch (__device__ globals; no cudaMalloc allowed) ----
__device__ __align__(16) float g_Mtab[NTAB * D];   // softmax(rel@W)/3 tables
__device__ __align__(16) float g_Weff[D * D];      // (circulant(loop_rel) @ loop_w)/3
__device__ __align__(16) float2 g_sedge[EMAX];     // CSR-sorted (row_as_int, norm)
__device__ int g_cnt[VMAX];
__device__ int g_off[VMAX + 1];
__device__ int g_cursor[VMAX];
__device__ int g_bsum[512];
__device__ int g_boff[512];
__device__ float g_sum[D];
__device__ float g_sumsq[D];
__device__ float g_scale[D];
__device__ float g_shift[D];

// ---- packed f32x2 helpers ----
__device__ __forceinline__ unsigned long long fma2(unsigned long long a,
                                                   unsigned long long b,
                                                   unsigned long long c) {
    unsigned long long d;
    asm("fma.rn.f32x2 %0, %1, %2, %3;" : "=l"(d) : "l"(a), "l"(b), "l"(c));
    return d;
}
__device__ __forceinline__ unsigned long long pack2(float lo, float hi) {
    unsigned long long d;
    asm("mov.b64 %0, {%1, %2};" : "=l"(d) : "f"(lo), "f"(hi));
    return d;
}
__device__ __forceinline__ void unpack2(unsigned long long v, float& lo, float& hi) {
    asm("mov.b64 {%0, %1}, %2;" : "=f"(lo), "=f"(hi) : "l"(v));
}
// 16B XOR swizzle on byte offsets for conflict-reduced float4 smem reads
__device__ __forceinline__ int sw16(int a) { return a ^ ((a >> 3) & 16); }

// ============================================================================
// zero counts + BN accumulators
// ============================================================================
__global__ void zero_kernel(int V) {
    int i = blockIdx.x * 256 + threadIdx.x;
    if (i < V) g_cnt[i] = 0;
    if (i < D) { g_sum[i] = 0.f; g_sumsq[i] = 0.f; }
}

__global__ void hist_kernel(const int* __restrict__ dst, int E) {
    int e = blockIdx.x * 256 + threadIdx.x;
    if (e < E) atomicAdd(&g_cnt[dst[e]], 1);
}

// ---- 2-level exclusive scan of g_cnt -> g_off ----
__global__ void scan1_kernel(int V) {
    __shared__ int sm[256];
    int t = threadIdx.x, i = blockIdx.x * 256 + t;
    sm[t] = (i < V) ? g_cnt[i] : 0;
    __syncthreads();
    for (int s = 128; s > 0; s >>= 1) {
        if (t < s) sm[t] += sm[t + s];
        __syncthreads();
    }
    if (t == 0) g_bsum[blockIdx.x] = sm[0];
}
__global__ void scan2_kernel(int NB) {
    __shared__ int sm[512];
    int t = threadIdx.x;
    int v0 = (t < NB) ? g_bsum[t] : 0;
    sm[t] = v0;
    __syncthreads();
    for (int s = 1; s < 512; s <<= 1) {
        int u = (t >= s) ? sm[t - s] : 0;
        __syncthreads();
        sm[t] += u;
        __syncthreads();
    }
    if (t < NB) g_boff[t] = sm[t] - v0;   // exclusive
}
__global__ void scan3_kernel(int V, int E) {
    __shared__ int sm[256];
    int b = blockIdx.x, t = threadIdx.x, i = b * 256 + t;
    int c = (i < V) ? g_cnt[i] : 0;
    sm[t] = c;
    __syncthreads();
    for (int s = 1; s < 256; s <<= 1) {
        int u = (t >= s) ? sm[t - s] : 0;
        __syncthreads();
        sm[t] += u;
        __syncthreads();
    }
    int excl = sm[t] - c + g_boff[b];
    if (i < V) { g_off[i] = excl; g_cursor[i] = excl; }
    if (i == V - 1) g_off[V] = E;
}

__global__ void sortscatter_kernel(const int* __restrict__ edge_type,
                                   const int* __restrict__ dst,
                                   const float* __restrict__ edge_norm,
                                   int E, int half) {
    int e = blockIdx.x * 256 + threadIdx.x;
    if (e >= E) return;
    int v = dst[e];
    int row = edge_type[e] + ((e >= half) ? NREL : 0);
    int pos = atomicAdd(&g_cursor[v], 1);
    g_sedge[pos] = make_float2(__int_as_float(row), edge_norm[e]);
}

// ============================================================================
// prep: g_Mtab (948 softmaxed msg rows /3), g_Weff, rel_out = rel_repr @ w_rel
// ============================================================================
__global__ void prep_kernel(const float* __restrict__ rel_repr,
                            const float* __restrict__ in_w,
                            const float* __restrict__ out_w,
                            const float* __restrict__ loop_w,
                            const float* __restrict__ w_rel,
                            const float* __restrict__ loop_rel,
                            float* __restrict__ rel_out) {
    __shared__ float rs[D];
    __shared__ float red[256];
    int b = blockIdx.x, tid = threadIdx.x;

    if (b < NTAB) {
        int t = (b < NREL) ? b : b - NREL;
        const float* W = (b < NREL) ? in_w : out_w;
        if (tid < D) rs[tid] = rel_repr[t * D + tid];
        __syncthreads();
        float acc = 0.f;
        if (tid < D) {
            #pragma unroll 4
            for (int k = 0; k < D; k++) acc = fmaf(rs[k], W[k * D + tid], acc);
        }
        red[tid] = (tid < D) ? acc : -1e30f;
        __syncthreads();
        for (int s = 128; s > 0; s >>= 1) {
            if (tid < s) red[tid] = fmaxf(red[tid], red[tid + s]);
            __syncthreads();
        }
        float mx = red[0];
        __syncthreads();
        float e = (tid < D) ? expf(acc - mx) : 0.f;
        red[tid] = e;
        __syncthreads();
        for (int s = 128; s > 0; s >>= 1) {
            if (tid < s) red[tid] += red[tid + s];
            __syncthreads();
        }
        float inv = 1.f / (red[0] * 3.f);
        if (tid < D) g_Mtab[b * D + tid] = e * inv;
    } else if (b < NTAB + D) {
        int kk = b - NTAB;
        if (tid < D) rs[tid] = loop_rel[tid];
        __syncthreads();
        if (tid < D) {
            float acc = 0.f;
            #pragma unroll 4
            for (int m = 0; m < D; m++) {
                int mm = m + kk; if (mm >= D) mm -= D;
                acc = fmaf(rs[mm], loop_w[m * D + tid], acc);
            }
            g_Weff[kk * D + tid] = acc * (1.f / 3.f);
        }
    } else {
        int t = b - (NTAB + D);
        if (tid < D) rs[tid] = rel_repr[t * D + tid];
        __syncthreads();
        if (tid < D) {
            float acc = 0.f;
            #pragma unroll 4
            for (int k = 0; k < D; k++) acc = fmaf(rs[k], w_rel[k * D + tid], acc);
            rel_out[t * D + tid] = acc;
        }
    }
}

// ============================================================================
// fused persistent kernel:
//   out[v] = x[v] @ Weff + bias + sum_{edges->v} norm_e * Mtab[row_e]
// plus fused BN statistics. Weff resident in smem (swizzled). 148 CTAs.
// Warp = 4 rows; lanes 0-24 own 8 cols each (lanes 25-31 shadow lane 24).
// Edge gather: 32 metas loaded coalesced per chunk, broadcast via shfl,
// Mtab rows streamed from L2 (fully resident, 758KB).
// ============================================================================
__global__ void __launch_bounds__(256, 1)
fused_kernel(const float* __restrict__ x,
             const float* __restrict__ bias,
             float* __restrict__ out, int V) {
    extern __shared__ float sm[];
    float* Ws = sm;                      // D*D swizzled (160000B)
    float* xs = sm + D * D;              // GR*D (25600B)
    float* sredS = xs + GR * D;          // 8*D
    float* sredQ = sredS + 8 * D;        // 8*D
    int tid = threadIdx.x;
    int team = tid >> 5;
    int lane = tid & 31;
    int cg = (lane < 25) ? lane : 24;
    bool active = (lane < 25);
    int j0 = cg * 8;

    char* Wb = reinterpret_cast<char*>(Ws);
    for (int i = tid; i < D * D; i += 256)
        *reinterpret_cast<float*>(Wb + sw16(i * 4)) = g_Weff[i];

    float b0[8];
    #pragma unroll
    for (int c = 0; c < 8; c++) b0[c] = bias[j0 + c];

    float s[8], q[8];
    #pragma unroll
    for (int c = 0; c < 8; c++) { s[c] = 0.f; q[c] = 0.f; }

    int ntiles = V / GR;
    for (int tile = blockIdx.x; tile < ntiles; tile += gridDim.x) {
        int row0 = tile * GR;
        __syncthreads();
        for (int i = tid; i < GR * D / 4; i += 256)
            reinterpret_cast<float4*>(xs)[i] =
                reinterpret_cast<const float4*>(x + (size_t)row0 * D)[i];
        __syncthreads();

        // ---- GEMM: 4 rows x 8 cols per thread, FFMA2 ----
        unsigned long long a[16];
        #pragma unroll
        for (int i = 0; i < 16; i++) a[i] = 0ull;
        const float* xrow = xs + team * 4 * D;
        #pragma unroll 2
        for (int k = 0; k < D; k++) {
            int base = (k * D + j0) * 4;
            float4 wa = *reinterpret_cast<const float4*>(Wb + sw16(base));
            float4 wb = *reinterpret_cast<const float4*>(Wb + sw16(base + 16));
            unsigned long long w0 = pack2(wa.x, wa.y);
            unsigned long long w1 = pack2(wa.z, wa.w);
            unsigned long long w2 = pack2(wb.x, wb.y);
            unsigned long long w3 = pack2(wb.z, wb.w);
            #pragma unroll
            for (int r = 0; r < 4; r++) {
                float xv = xrow[r * D + k];
                unsigned long long xx = pack2(xv, xv);
                a[r * 4 + 0] = fma2(xx, w0, a[r * 4 + 0]);
                a[r * 4 + 1] = fma2(xx, w1, a[r * 4 + 1]);
                a[r * 4 + 2] = fma2(xx, w2, a[r * 4 + 2]);
                a[r * 4 + 3] = fma2(xx, w3, a[r * 4 + 3]);
            }
        }

        // ---- edge gather for this warp's 4 vertices ----
        #pragma unroll
        for (int r = 0; r < 4; r++) {
            int v = row0 + team * 4 + r;
            int e0 = g_off[v], e1 = g_off[v + 1];
            for (int bse = e0; bse < e1; bse += 32) {
                int n = e1 - bse; if (n > 32) n = 32;
                float2 ed = (bse + lane < e1) ? g_sedge[bse + lane]
                                              : make_float2(0.f, 0.f);
                for (int j = 0; j < n; j++) {
                    int row = __shfl_sync(0xffffffffu, __float_as_int(ed.x), j);
                    float nm = __shfl_sync(0xffffffffu, ed.y, j);
                    const float4* tp =
                        reinterpret_cast<const float4*>(g_Mtab + row * D + j0);
                    float4 t0 = tp[0];
                    float4 t1 = tp[1];
                    unsigned long long nn = pack2(nm, nm);
                    a[r * 4 + 0] = fma2(nn, pack2(t0.x, t0.y), a[r * 4 + 0]);
                    a[r * 4 + 1] = fma2(nn, pack2(t0.z, t0.w), a[r * 4 + 1]);
                    a[r * 4 + 2] = fma2(nn, pack2(t1.x, t1.y), a[r * 4 + 2]);
                    a[r * 4 + 3] = fma2(nn, pack2(t1.z, t1.w), a[r * 4 + 3]);
                }
            }
        }

        // ---- epilogue: bias, store, BN partials ----
        if (active) {
            #pragma unroll
            for (int r = 0; r < 4; r++) {
                float v[8];
                unpack2(a[r * 4 + 0], v[0], v[1]);
                unpack2(a[r * 4 + 1], v[2], v[3]);
                unpack2(a[r * 4 + 2], v[4], v[5]);
                unpack2(a[r * 4 + 3], v[6], v[7]);
                #pragma unroll
                for (int c = 0; c < 8; c++) {
                    v[c] += b0[c];
                    s[c] += v[c];
                    q[c] += v[c] * v[c];
                }
                float* op = out + (size_t)(row0 + team * 4 + r) * D + j0;
                *reinterpret_cast<float4*>(op) =
                    make_float4(v[0], v[1], v[2], v[3]);
                *reinterpret_cast<float4*>(op + 4) =
                    make_float4(v[4], v[5], v[6], v[7]);
            }
        }
    }

    // ---- block-level BN reduction, one atomic per column per block ----
    __syncthreads();
    if (active) {
        #pragma unroll
        for (int c = 0; c < 8; c++) {
            sredS[team * D + j0 + c] = s[c];
            sredQ[team * D + j0 + c] = q[c];
        }
    }
    __syncthreads();
    if (tid < D) {
        float ts = 0.f, tq = 0.f;
        #pragma unroll
        for (int t = 0; t < 8; t++) {
            ts += sredS[t * D + tid];
            tq += sredQ[t * D + tid];
        }
        atomicAdd(&g_sum[tid], ts);
        atomicAdd(&g_sumsq[tid], tq);
    }
}

// ============================================================================
// BN params + final normalize
// ============================================================================
__global__ void bn_params_kernel(const float* __restrict__ bn_w,
                                 const float* __restrict__ bn_b, float invV) {
    int j = threadIdx.x;
    if (j < D) {
        float mean = g_sum[j] * invV;
        float var = g_sumsq[j] * invV - mean * mean;
        float sc = bn_w[j] * rsqrtf(var + 1e-5f);
        g_scale[j] = sc;
        g_shift[j] = bn_b[j] - mean * sc;
    }
}

__global__ void bn_final_kernel(float* __restrict__ out, int total4) {
    int i = blockIdx.x * 256 + threadIdx.x;
    if (i >= total4) return;
    int c0 = (i % 50) * 4;
    float4 v = reinterpret_cast<float4*>(out)[i];
    v.x = v.x * g_scale[c0]     + g_shift[c0];
    v.y = v.y * g_scale[c0 + 1] + g_shift[c0 + 1];
    v.z = v.z * g_scale[c0 + 2] + g_shift[c0 + 2];
    v.w = v.w * g_scale[c0 + 3] + g_shift[c0 + 3];
    reinterpret_cast<float4*>(out)[i] = v;
}

// ============================================================================
extern "C" void kernel_launch(void* const* d_in, const int* in_sizes, int n_in,
                              void* d_out, int out_size) {
    const float* x         = (const float*)d_in[0];
    const float* rel_repr  = (const float*)d_in[1];
    const float* edge_norm = (const float*)d_in[2];
    const float* in_w      = (const float*)d_in[3];
    const float* out_w     = (const float*)d_in[4];
    const float* loop_w    = (const float*)d_in[5];
    const float* w_rel     = (const float*)d_in[6];
    const float* loop_rel  = (const float*)d_in[7];
    const float* bias      = (const float*)d_in[8];
    const float* bn_w      = (const float*)d_in[9];
    const float* bn_b      = (const float*)d_in[10];
    const int*   edge_type = (const int*)d_in[11];
    const int*   dst       = (const int*)d_in[12];
    float* out = (float*)d_out;

    int V = in_sizes[0] / D;           // 100000
    int E = in_sizes[2];               // 1000000
    float* rel_out = out + (size_t)V * D;
    int NB = (V + 255) / 256;          // 391

    size_t smem_fused = (size_t)(D * D + GR * D + 16 * D) * sizeof(float); // ~198.4KB
    cudaFuncSetAttribute(fused_kernel,
                         cudaFuncAttributeMaxDynamicSharedMemorySize, (int)smem_fused);

    // CSR sort of edges by dst
    zero_kernel<<<NB, 256>>>(V);
    hist_kernel<<<(E + 255) / 256, 256>>>(dst, E);
    scan1_kernel<<<NB, 256>>>(V);
    scan2_kernel<<<1, 512>>>(NB);
    scan3_kernel<<<NB, 256>>>(V, E);
    sortscatter_kernel<<<(E + 255) / 256, 256>>>(edge_type, dst, edge_norm, E, E / 2);

    // message tables + folded self-loop weight + rel_out
    prep_kernel<<<NTAB + D + NREL, 256>>>(rel_repr, in_w, out_w, loop_w,
                                          w_rel, loop_rel, rel_out);
    // fused: out = x@Weff + bias + gathered messages; BN stats accumulated
    fused_kernel<<<148, 256, smem_fused>>>(x, bias, out, V);
    // batchnorm finalize
    bn_params_kernel<<<1, 256>>>(bn_w, bn_b, 1.f / (float)V);
    int total4 = V * (D / 4);
    bn_final_kernel<<<(total4 + 255) / 256, 256>>>(out, total4);
}

// round 4
// speedup vs baseline: 3.3871x; 1.1911x over previous
#include <cuda_runtime.h>
#include <cstdint>

#define D 200
#define NREL 474
#define NTAB 948
#define VMAX 100000
#define EMAX 1000000
#define THREADS 512
#define NCTA 148
#define TILE 64            // rows per tile: 16 warps x 4 rows
#define CHUNK 676          // ceil(VMAX/NCTA)

typedef unsigned long long ull;

// ---- device scratch (no cudaMalloc allowed) ----
__device__ __align__(16) float g_Mtab[NTAB * D];
__device__ __align__(16) float g_Weff[D * D];
__device__ __align__(16) float2 g_sedge[EMAX];
__device__ int g_cnt[VMAX];
__device__ int g_off[VMAX + 1];
__device__ int g_cursor[VMAX];
__device__ int g_bsum[NCTA];
__device__ int g_boff[NCTA];
__device__ float g_sum[D], g_sumsq[D];
__device__ unsigned g_barGen, g_barCnt;
__device__ int g_ticket;

// ---- packed f32x2 ----
__device__ __forceinline__ ull fma2(ull a, ull b, ull c) {
    ull d;
    asm("fma.rn.f32x2 %0, %1, %2, %3;" : "=l"(d) : "l"(a), "l"(b), "l"(c));
    return d;
}
__device__ __forceinline__ ull pack2(float lo, float hi) {
    ull d;
    asm("mov.b64 %0, {%1, %2};" : "=l"(d) : "f"(lo), "f"(hi));
    return d;
}
__device__ __forceinline__ void unpack2(ull v, float& lo, float& hi) {
    asm("mov.b64 {%0, %1}, %2;" : "=f"(lo), "=f"(hi) : "l"(v));
}
__device__ __forceinline__ int sw16(int a) { return a ^ ((a >> 3) & 16); }

// ---- generation grid barrier (all 148 CTAs co-resident) ----
__device__ __forceinline__ void grid_bar() {
    __syncthreads();
    if (threadIdx.x == 0) {
        unsigned gen = *(volatile unsigned*)&g_barGen;
        __threadfence();
        if (atomicAdd(&g_barCnt, 1u) == NCTA - 1) {
            g_barCnt = 0;
            __threadfence();
            atomicExch(&g_barGen, gen + 1);
        } else {
            while (*(volatile unsigned*)&g_barGen == gen) __nanosleep(32);
        }
    }
    __syncthreads();
    __threadfence();   // gpu-scope: CCTL.IVALL flushes L1D -> no stale lines
}

// ============================================================================
__global__ void __launch_bounds__(THREADS, 1)
mega_kernel(const float* __restrict__ x,
            const float* __restrict__ rel_repr,
            const float* __restrict__ edge_norm,
            const float* __restrict__ in_w,
            const float* __restrict__ out_w,
            const float* __restrict__ loop_w,
            const float* __restrict__ w_rel,
            const float* __restrict__ loop_rel,
            const float* __restrict__ bias,
            const float* __restrict__ bn_w,
            const float* __restrict__ bn_b,
            const int* __restrict__ edge_type,
            const int* __restrict__ dst,
            float* __restrict__ out, int V, int E) {
    extern __shared__ float dynF[];          // [0,D*D): W ; then TILE*D xs
    float* xsF = dynF + D * D;
    char*  Wb  = reinterpret_cast<char*>(dynF);
    __shared__ int   ism[THREADS];
    __shared__ int   s2[256];
    __shared__ float fred[THREADS];
    __shared__ float rs[D];
    __shared__ int   ibroad;

    const int tid  = threadIdx.x;
    const int cta  = blockIdx.x;
    const int lane = tid & 31;
    const int team = tid >> 5;               // 16 warps
    const int cg   = (lane < 25) ? lane : 24;
    const bool alane = (lane < 25);
    const int j0   = cg * 8;
    const int halfE = E / 2;
    float* rel_out = out + (size_t)V * D;

    // ---------------- phase 0: zero ----------------
    for (int i = cta * THREADS + tid; i < V; i += NCTA * THREADS) g_cnt[i] = 0;
    if (cta == 0) {
        if (tid < D) { g_sum[tid] = 0.f; g_sumsq[tid] = 0.f; }
        if (tid == 0) g_ticket = 0;
    }
    grid_bar();

    // ---------------- phase 1: histogram of dst ----------------
    for (int e = cta * THREADS + tid; e < E; e += NCTA * THREADS)
        atomicAdd(&g_cnt[dst[e]], 1);
    grid_bar();

    // ---------------- phase 2: scan ----------------
    const int c0 = cta * CHUNK;
    int i0 = c0 + tid * 2;
    bool v0ok = (tid * 2 < CHUNK) && (i0 < V);
    bool v1ok = (tid * 2 + 1 < CHUNK) && (i0 + 1 < V);
    int ca = v0ok ? g_cnt[i0] : 0;
    int cb = v1ok ? g_cnt[i0 + 1] : 0;
    int local = ca + cb;
    ism[tid] = local;
    __syncthreads();
    for (int s = 1; s < THREADS; s <<= 1) {
        int u = (tid >= s) ? ism[tid - s] : 0;
        __syncthreads();
        ism[tid] += u;
        __syncthreads();
    }
    if (tid == THREADS - 1) g_bsum[cta] = ism[THREADS - 1];
    grid_bar();

    if (cta == 0) {
        int v = (tid < NCTA) ? g_bsum[tid] : 0;
        if (tid < 256) s2[tid] = v;
        __syncthreads();
        for (int s = 1; s < 256; s <<= 1) {
            int u = (tid >= s && tid < 256) ? s2[tid - s] : 0;
            __syncthreads();
            if (tid < 256) s2[tid] += u;
            __syncthreads();
        }
        if (tid < NCTA) g_boff[tid] = s2[tid] - v;
        if (tid == 0) g_off[V] = E;
    }
    grid_bar();

    {
        int base = ism[tid] - local + g_boff[cta];
        if (v0ok) { g_off[i0] = base;          g_cursor[i0] = base; }
        if (v1ok) { g_off[i0 + 1] = base + ca; g_cursor[i0 + 1] = base + ca; }
    }
    grid_bar();

    // ---------------- phase 3: sortscatter + prep ----------------
    for (int e = cta * THREADS + tid; e < E; e += NCTA * THREADS) {
        int v = dst[e];
        int row = edge_type[e] + ((e >= halfE) ? NREL : 0);
        int pos = atomicAdd(&g_cursor[v], 1);
        g_sedge[pos] = make_float2(__int_as_float(row), edge_norm[e]);
    }

    {   // prep: 4 tasks per weight sweep
        const int nb = (NREL + 3) / 4;       // 119
        const int totalB = nb * 2 + (D / 4) + nb;
        for (int bb = cta; bb < totalB; bb += NCTA) {
            if (bb < 2 * nb) {
                int hh = bb / nb;
                int b4 = (bb % nb) * 4;
                const float* W = hh ? out_w : in_w;
                for (int i = tid; i < 4 * D; i += THREADS) {
                    int j = i / D, k = i - j * D;
                    int t = b4 + j;
                    xsF[i] = (t < NREL) ? rel_repr[t * D + k] : 0.f;
                }
                __syncthreads();
                float acc[4] = {0.f, 0.f, 0.f, 0.f};
                if (tid < D) {
                    for (int k = 0; k < D; k++) {
                        float wv = W[k * D + tid];
                        #pragma unroll
                        for (int j = 0; j < 4; j++)
                            acc[j] = fmaf(xsF[j * D + k], wv, acc[j]);
                    }
                }
                float ee[4], inv[4];
                #pragma unroll
                for (int j = 0; j < 4; j++) {
                    fred[tid] = (tid < D) ? acc[j] : -1e30f;
                    __syncthreads();
                    for (int s = 256; s > 0; s >>= 1) {
                        if (tid < s) fred[tid] = fmaxf(fred[tid], fred[tid + s]);
                        __syncthreads();
                    }
                    float mx = fred[0];
                    __syncthreads();
                    ee[j] = (tid < D) ? expf(acc[j] - mx) : 0.f;
                    fred[tid] = ee[j];
                    __syncthreads();
                    for (int s = 256; s > 0; s >>= 1) {
                        if (tid < s) fred[tid] += fred[tid + s];
                        __syncthreads();
                    }
                    inv[j] = 1.f / (fred[0] * 3.f);
                    __syncthreads();
                }
                if (tid < D) {
                    #pragma unroll
                    for (int j = 0; j < 4; j++) {
                        int t = b4 + j;
                        if (t < NREL)
                            g_Mtab[(hh * NREL + t) * D + tid] = ee[j] * inv[j];
                    }
                }
                __syncthreads();
            } else if (bb < 2 * nb + D / 4) {
                int kk0 = (bb - 2 * nb) * 4;
                if (tid < D) rs[tid] = loop_rel[tid];
                __syncthreads();
                if (tid < D) {
                    float acc[4] = {0.f, 0.f, 0.f, 0.f};
                    for (int m = 0; m < D; m++) {
                        float wv = loop_w[m * D + tid];
                        #pragma unroll
                        for (int j = 0; j < 4; j++) {
                            int mm = m + kk0 + j;
                            if (mm >= D) mm -= D;
                            acc[j] = fmaf(rs[mm], wv, acc[j]);
                        }
                    }
                    #pragma unroll
                    for (int j = 0; j < 4; j++)
                        g_Weff[(kk0 + j) * D + tid] = acc[j] * (1.f / 3.f);
                }
                __syncthreads();
            } else {
                int b4 = (bb - 2 * nb - D / 4) * 4;
                for (int i = tid; i < 4 * D; i += THREADS) {
                    int j = i / D, k = i - j * D;
                    int t = b4 + j;
                    xsF[i] = (t < NREL) ? rel_repr[t * D + k] : 0.f;
                }
                __syncthreads();
                if (tid < D) {
                    float acc[4] = {0.f, 0.f, 0.f, 0.f};
                    for (int k = 0; k < D; k++) {
                        float wv = w_rel[k * D + tid];
                        #pragma unroll
                        for (int j = 0; j < 4; j++)
                            acc[j] = fmaf(xsF[j * D + k], wv, acc[j]);
                    }
                    #pragma unroll
                    for (int j = 0; j < 4; j++)
                        if (b4 + j < NREL) rel_out[(b4 + j) * D + tid] = acc[j];
                }
                __syncthreads();
            }
        }
    }
    grid_bar();

    // ---------------- phase 4: main GEMM + gather + BN stats ----------------
    for (int i = tid; i < D * D; i += THREADS)
        *reinterpret_cast<float*>(Wb + sw16(i * 4)) = g_Weff[i];

    float b0[8];
    #pragma unroll
    for (int c = 0; c < 8; c++) b0[c] = bias[j0 + c];
    float sS[8], sQ[8];
    #pragma unroll
    for (int c = 0; c < 8; c++) { sS[c] = 0.f; sQ[c] = 0.f; }

    const int ntiles = (V + TILE - 1) / TILE;
    for (;;) {
        __syncthreads();
        if (tid == 0) ibroad = atomicAdd(&g_ticket, 1);
        __syncthreads();
        int tile = ibroad;
        if (tile >= ntiles) break;
        int row0 = tile * TILE;

        for (int i = tid; i < TILE * 50; i += THREADS) {
            int r = row0 + i / 50;
            float4 v = (r < V)
                ? reinterpret_cast<const float4*>(x)[(size_t)r * 50 + (i % 50)]
                : make_float4(0.f, 0.f, 0.f, 0.f);
            reinterpret_cast<float4*>(xsF)[i] = v;
        }
        __syncthreads();

        ull a[16];
        #pragma unroll
        for (int i = 0; i < 16; i++) a[i] = 0ull;
        const float* xrow = xsF + team * 4 * D;
        #pragma unroll 2
        for (int k = 0; k < D; k++) {
            int base = (k * D + j0) * 4;
            ulonglong2 wA = *reinterpret_cast<const ulonglong2*>(Wb + sw16(base));
            ulonglong2 wB = *reinterpret_cast<const ulonglong2*>(Wb + sw16(base + 16));
            #pragma unroll
            for (int r = 0; r < 4; r++) {
                float xv = xrow[r * D + k];
                ull xx = pack2(xv, xv);
                a[r * 4 + 0] = fma2(xx, wA.x, a[r * 4 + 0]);
                a[r * 4 + 1] = fma2(xx, wA.y, a[r * 4 + 1]);
                a[r * 4 + 2] = fma2(xx, wB.x, a[r * 4 + 2]);
                a[r * 4 + 3] = fma2(xx, wB.y, a[r * 4 + 3]);
            }
        }

        #pragma unroll
        for (int r = 0; r < 4; r++) {
            int vrow = row0 + team * 4 + r;
            if (vrow >= V) break;                   // warp-uniform
            int e0 = g_off[vrow], e1 = g_off[vrow + 1];
            for (int bse = e0; bse < e1; bse += 32) {
                int n = e1 - bse; if (n > 32) n = 32;
                float2 ed = (bse + lane < e1) ? g_sedge[bse + lane]
                                              : make_float2(0.f, 0.f);
                int rowm = __float_as_int(ed.x);
                for (int j = 0; j < n; j++) {
                    int rr = __shfl_sync(0xffffffffu, rowm, j);
                    float nm = __shfl_sync(0xffffffffu, ed.y, j);
                    const float4* tp =
                        reinterpret_cast<const float4*>(g_Mtab + rr * D + j0);
                    float4 t0 = tp[0];
                    float4 t1 = tp[1];
                    ull nn = pack2(nm, nm);
                    a[r * 4 + 0] = fma2(nn, pack2(t0.x, t0.y), a[r * 4 + 0]);
                    a[r * 4 + 1] = fma2(nn, pack2(t0.z, t0.w), a[r * 4 + 1]);
                    a[r * 4 + 2] = fma2(nn, pack2(t1.x, t1.y), a[r * 4 + 2]);
                    a[r * 4 + 3] = fma2(nn, pack2(t1.z, t1.w), a[r * 4 + 3]);
                }
            }
        }

        #pragma unroll
        for (int r = 0; r < 4; r++) {
            int vrow = row0 + team * 4 + r;
            if (alane && vrow < V) {
                float v[8];
                unpack2(a[r * 4 + 0], v[0], v[1]);
                unpack2(a[r * 4 + 1], v[2], v[3]);
                unpack2(a[r * 4 + 2], v[4], v[5]);
                unpack2(a[r * 4 + 3], v[6], v[7]);
                #pragma unroll
                for (int c = 0; c < 8; c++) {
                    v[c] += b0[c];
                    sS[c] += v[c];
                    sQ[c] += v[c] * v[c];
                }
                float* op = out + (size_t)vrow * D + j0;
                *reinterpret_cast<float4*>(op)     = make_float4(v[0], v[1], v[2], v[3]);
                *reinterpret_cast<float4*>(op + 4) = make_float4(v[4], v[5], v[6], v[7]);
            }
        }
    }

    __syncthreads();
    if (alane) {
        #pragma unroll
        for (int c = 0; c < 8; c++) xsF[team * D + j0 + c] = sS[c];
    }
    __syncthreads();
    if (tid < D) {
        float t = 0.f;
        #pragma unroll
        for (int w = 0; w < 16; w++) t += xsF[w * D + tid];
        atomicAdd(&g_sum[tid], t);
    }
    __syncthreads();
    if (alane) {
        #pragma unroll
        for (int c = 0; c < 8; c++) xsF[team * D + j0 + c] = sQ[c];
    }
    __syncthreads();
    if (tid < D) {
        float t = 0.f;
        #pragma unroll
        for (int w = 0; w < 16; w++) t += xsF[w * D + tid];
        atomicAdd(&g_sumsq[tid], t);
    }
    grid_bar();

    // ---------------- phase 5: BN normalize ----------------
    {
        float invV = 1.f / (float)V;
        if (tid < D) {
            float mean = g_sum[tid] * invV;
            float var = g_sumsq[tid] * invV - mean * mean;
            float sc = bn_w[tid] * rsqrtf(var + 1e-5f);
            rs[tid] = sc;
            fred[tid] = bn_b[tid] - mean * sc;
        }
        __syncthreads();
        int r0 = cta * CHUNK;
        for (int i = tid; i < CHUNK * 50; i += THREADS) {
            int r = r0 + i / 50;
            if (r < V) {
                int c4 = (i % 50) * 4;
                float4* p = reinterpret_cast<float4*>(out + (size_t)r * D + c4);
                float4 v = *p;
                v.x = v.x * rs[c4]     + fred[c4];
                v.y = v.y * rs[c4 + 1] + fred[c4 + 1];
                v.z = v.z * rs[c4 + 2] + fred[c4 + 2];
                v.w = v.w * rs[c4 + 3] + fred[c4 + 3];
                *p = v;
            }
        }
    }
}

// ============================================================================
extern "C" void kernel_launch(void* const* d_in, const int* in_sizes, int n_in,
                              void* d_out, int out_size) {
    const float* x         = (const float*)d_in[0];
    const float* rel_repr  = (const float*)d_in[1];
    const float* edge_norm = (const float*)d_in[2];
    const float* in_w      = (const float*)d_in[3];
    const float* out_w     = (const float*)d_in[4];
    const float* loop_w    = (const float*)d_in[5];
    const float* w_rel     = (const float*)d_in[6];
    const float* loop_rel  = (const float*)d_in[7];
    const float* bias      = (const float*)d_in[8];
    const float* bn_w      = (const float*)d_in[9];
    const float* bn_b      = (const float*)d_in[10];
    const int*   edge_type = (const int*)d_in[11];
    const int*   dst       = (const int*)d_in[12];
    float* out = (float*)d_out;

    int V = in_sizes[0] / D;   // 100000
    int E = in_sizes[2];       // 1000000

    size_t smem = (size_t)(D * D + TILE * D) * sizeof(float);   // 211,200 B
    cudaFuncSetAttribute(mega_kernel,
                         cudaFuncAttributeMaxDynamicSharedMemorySize, (int)smem);

    mega_kernel<<<NCTA, THREADS, smem>>>(x, rel_repr, edge_norm, in_w, out_w,
                                         loop_w, w_rel, loop_rel, bias, bn_w,
                                         bn_b, edge_type, dst, out, V, E);
}

// round 7
// speedup vs baseline: 3.5227x; 1.0400x over previous
#include <cuda_runtime.h>
#include <cstdint>

#define D 200
#define NREL 474
#define NTAB 948
#define VMAX 100000
#define EMAX 1000000
#define THREADS 512
#define NCTA 148
#define TILE 64            // rows per tile: 8 row-groups x 8 rows
#define CHUNK 676          // ceil(VMAX/NCTA)

typedef unsigned long long ull;

// ---- device scratch (no cudaMalloc allowed) ----
__device__ __align__(16) float g_Mtab[NTAB * D];
__device__ __align__(16) float g_Weff[D * D];
__device__ __align__(16) float2 g_sedge[EMAX];
__device__ int g_cnt[VMAX];
__device__ int g_off[VMAX + 1];
__device__ int g_cursor[VMAX];
__device__ int g_bsum[NCTA];
__device__ int g_boff[NCTA];
__device__ float g_sum[D], g_sumsq[D];
__device__ unsigned g_barGen, g_barCnt;
__device__ int g_ticket, g_ticket2;

// ---- packed f32x2 ----
__device__ __forceinline__ ull fma2(ull a, ull b, ull c) {
    ull d;
    asm("fma.rn.f32x2 %0, %1, %2, %3;" : "=l"(d) : "l"(a), "l"(b), "l"(c));
    return d;
}
__device__ __forceinline__ ull pack2(float lo, float hi) {
    ull d;
    asm("mov.b64 %0, {%1, %2};" : "=l"(d) : "f"(lo), "f"(hi));
    return d;
}
__device__ __forceinline__ void unpack2(ull v, float& lo, float& hi) {
    asm("mov.b64 {%0, %1}, %2;" : "=f"(lo), "=f"(hi) : "l"(v));
}

// ---- generation grid barrier (all 148 CTAs co-resident) ----
__device__ __forceinline__ void grid_bar() {
    __syncthreads();
    if (threadIdx.x == 0) {
        unsigned gen = *(volatile unsigned*)&g_barGen;
        __threadfence();
        if (atomicAdd(&g_barCnt, 1u) == NCTA - 1) {
            g_barCnt = 0;
            __threadfence();
            atomicExch(&g_barGen, gen + 1);
        } else {
            while (*(volatile unsigned*)&g_barGen == gen) __nanosleep(32);
        }
    }
    __syncthreads();
    __threadfence();   // gpu-scope: flush L1D -> no stale lines across phases
}

// ============================================================================
__global__ void __launch_bounds__(THREADS, 1)
mega_kernel(const float* __restrict__ x,
            const float* __restrict__ rel_repr,
            const float* __restrict__ edge_norm,
            const float* __restrict__ in_w,
            const float* __restrict__ out_w,
            const float* __restrict__ loop_w,
            const float* __restrict__ w_rel,
            const float* __restrict__ loop_rel,
            const float* __restrict__ bias,
            const float* __restrict__ bn_w,
            const float* __restrict__ bn_b,
            const int* __restrict__ edge_type,
            const int* __restrict__ dst,
            float* __restrict__ out, int V, int E) {
    extern __shared__ float dynF[];          // [0,D*D): W ; then TILE*D xs
    float* xsF = dynF + D * D;
    __shared__ int   ism[THREADS];
    __shared__ int   s2[256];
    __shared__ float fred[THREADS];
    __shared__ float rs[D];
    __shared__ int   ibroad;

    const int tid  = threadIdx.x;
    const int cta  = blockIdx.x;
    const int lane = tid & 31;
    const int team = tid >> 5;               // 16 warps
    const int cg   = (lane < 25) ? lane : 24;
    const bool alane = (lane < 25);
    const int halfE = E / 2;
    float* rel_out = out + (size_t)V * D;

    // GEMM column mapping: warp pair splits columns
    const int teamR   = team >> 1;           // 8 row groups (8 rows each)
    const int colhalf = team & 1;            // 2 column halves of 100
    const int jg      = colhalf * 100 + cg * 4;   // 4 cols per lane (GEMM)
    // gather column mapping: 8 cols per lane
    const int j0 = cg * 8;

    // ---------------- phase 0: zero ----------------
    for (int i = cta * THREADS + tid; i < V; i += NCTA * THREADS) g_cnt[i] = 0;
    if (cta == 0) {
        if (tid < D) { g_sum[tid] = 0.f; g_sumsq[tid] = 0.f; }
        if (tid == 0) { g_ticket = 0; g_ticket2 = 0; }
    }
    grid_bar();

    // ---------------- phase 1: histogram of dst ----------------
    for (int e = cta * THREADS + tid; e < E; e += NCTA * THREADS)
        atomicAdd(&g_cnt[dst[e]], 1);
    grid_bar();

    // ---------------- phase 2: scan ----------------
    const int c0 = cta * CHUNK;
    int i0 = c0 + tid * 2;
    bool v0ok = (tid * 2 < CHUNK) && (i0 < V);
    bool v1ok = (tid * 2 + 1 < CHUNK) && (i0 + 1 < V);
    int ca = v0ok ? g_cnt[i0] : 0;
    int cb = v1ok ? g_cnt[i0 + 1] : 0;
    int local = ca + cb;
    ism[tid] = local;
    __syncthreads();
    for (int s = 1; s < THREADS; s <<= 1) {
        int u = (tid >= s) ? ism[tid - s] : 0;
        __syncthreads();
        ism[tid] += u;
        __syncthreads();
    }
    if (tid == THREADS - 1) g_bsum[cta] = ism[THREADS - 1];
    grid_bar();

    if (cta == 0) {
        int v = (tid < NCTA) ? g_bsum[tid] : 0;
        if (tid < 256) s2[tid] = v;
        __syncthreads();
        for (int s = 1; s < 256; s <<= 1) {
            int u = (tid >= s && tid < 256) ? s2[tid - s] : 0;
            __syncthreads();
            if (tid < 256) s2[tid] += u;
            __syncthreads();
        }
        if (tid < NCTA) g_boff[tid] = s2[tid] - v;
        if (tid == 0) g_off[V] = E;
    }
    grid_bar();

    {
        int base = ism[tid] - local + g_boff[cta];
        if (v0ok) { g_off[i0] = base;          g_cursor[i0] = base; }
        if (v1ok) { g_off[i0 + 1] = base + ca; g_cursor[i0 + 1] = base + ca; }
    }
    grid_bar();

    // ---------------- phase 3: sortscatter + prep ----------------
    for (int e = cta * THREADS + tid; e < E; e += NCTA * THREADS) {
        int v = dst[e];
        int row = edge_type[e] + ((e >= halfE) ? NREL : 0);
        int pos = atomicAdd(&g_cursor[v], 1);
        g_sedge[pos] = make_float2(__int_as_float(row), edge_norm[e]);
    }

    {   // prep: 4 tasks per weight sweep (scratch = xsF)
        const int nb = (NREL + 3) / 4;       // 119
        const int totalB = nb * 2 + (D / 4) + nb;
        for (int bb = cta; bb < totalB; bb += NCTA) {
            if (bb < 2 * nb) {
                int hh = bb / nb;
                int b4 = (bb % nb) * 4;
                const float* W = hh ? out_w : in_w;
                for (int i = tid; i < 4 * D; i += THREADS) {
                    int j = i / D, k = i - j * D;
                    int t = b4 + j;
                    xsF[i] = (t < NREL) ? rel_repr[t * D + k] : 0.f;
                }
                __syncthreads();
                float acc[4] = {0.f, 0.f, 0.f, 0.f};
                if (tid < D) {
                    for (int k = 0; k < D; k++) {
                        float wv = W[k * D + tid];
                        #pragma unroll
                        for (int j = 0; j < 4; j++)
                            acc[j] = fmaf(xsF[j * D + k], wv, acc[j]);
                    }
                }
                float ee[4], inv[4];
                #pragma unroll
                for (int j = 0; j < 4; j++) {
                    fred[tid] = (tid < D) ? acc[j] : -1e30f;
                    __syncthreads();
                    for (int s = 256; s > 0; s >>= 1) {
                        if (tid < s) fred[tid] = fmaxf(fred[tid], fred[tid + s]);
                        __syncthreads();
                    }
                    float mx = fred[0];
                    __syncthreads();
                    ee[j] = (tid < D) ? expf(acc[j] - mx) : 0.f;
                    fred[tid] = ee[j];
                    __syncthreads();
                    for (int s = 256; s > 0; s >>= 1) {
                        if (tid < s) fred[tid] += fred[tid + s];
                        __syncthreads();
                    }
                    inv[j] = 1.f / (fred[0] * 3.f);
                    __syncthreads();
                }
                if (tid < D) {
                    #pragma unroll
                    for (int j = 0; j < 4; j++) {
                        int t = b4 + j;
                        if (t < NREL)
                            g_Mtab[(hh * NREL + t) * D + tid] = ee[j] * inv[j];
                    }
                }
                __syncthreads();
            } else if (bb < 2 * nb + D / 4) {
                int kk0 = (bb - 2 * nb) * 4;
                if (tid < D) rs[tid] = loop_rel[tid];
                __syncthreads();
                if (tid < D) {
                    float acc[4] = {0.f, 0.f, 0.f, 0.f};
                    for (int m = 0; m < D; m++) {
                        float wv = loop_w[m * D + tid];
                        #pragma unroll
                        for (int j = 0; j < 4; j++) {
                            int mm = m + kk0 + j;
                            if (mm >= D) mm -= D;
                            acc[j] = fmaf(rs[mm], wv, acc[j]);
                        }
                    }
                    #pragma unroll
                    for (int j = 0; j < 4; j++)
                        g_Weff[(kk0 + j) * D + tid] = acc[j] * (1.f / 3.f);
                }
                __syncthreads();
            } else {
                int b4 = (bb - 2 * nb - D / 4) * 4;
                for (int i = tid; i < 4 * D; i += THREADS) {
                    int j = i / D, k = i - j * D;
                    int t = b4 + j;
                    xsF[i] = (t < NREL) ? rel_repr[t * D + k] : 0.f;
                }
                __syncthreads();
                if (tid < D) {
                    float acc[4] = {0.f, 0.f, 0.f, 0.f};
                    for (int k = 0; k < D; k++) {
                        float wv = w_rel[k * D + tid];
                        #pragma unroll
                        for (int j = 0; j < 4; j++)
                            acc[j] = fmaf(xsF[j * D + k], wv, acc[j]);
                    }
                    #pragma unroll
                    for (int j = 0; j < 4; j++)
                        if (b4 + j < NREL) rel_out[(b4 + j) * D + tid] = acc[j];
                }
                __syncthreads();
            }
        }
    }
    grid_bar();

    // ---------------- phase 4: GEMM out = x@Weff + bias ----------------
    // W resident in smem (plain layout: 16B-stride lane access is phase-
    // conflict-free, no swizzle). 8 rows x 4 cols per thread, FFMA2.
    for (int i = tid; i < D * D; i += THREADS) dynF[i] = g_Weff[i];

    {
        float b0[4];
        #pragma unroll
        for (int c = 0; c < 4; c++) b0[c] = bias[jg + c];

        const int ntiles = (V + TILE - 1) / TILE;
        for (;;) {
            __syncthreads();
            if (tid == 0) ibroad = atomicAdd(&g_ticket, 1);
            __syncthreads();
            int tile = ibroad;
            if (tile >= ntiles) break;
            int row0 = tile * TILE;

            for (int i = tid; i < TILE * 50; i += THREADS) {
                int r = row0 + i / 50;
                float4 v = (r < V)
                    ? reinterpret_cast<const float4*>(x)[(size_t)r * 50 + (i % 50)]
                    : make_float4(0.f, 0.f, 0.f, 0.f);
                reinterpret_cast<float4*>(xsF)[i] = v;
            }
            __syncthreads();

            ull a[16];                         // 8 rows x 2 fma2 (4 cols)
            #pragma unroll
            for (int i = 0; i < 16; i++) a[i] = 0ull;
            const float* xrow = xsF + teamR * 8 * D;
            #pragma unroll 2
            for (int k = 0; k < D; k += 2) {
                ulonglong2 w0 = *reinterpret_cast<const ulonglong2*>(dynF + k * D + jg);
                ulonglong2 w1 = *reinterpret_cast<const ulonglong2*>(dynF + (k + 1) * D + jg);
                #pragma unroll
                for (int r = 0; r < 8; r++) {
                    float2 xv = *reinterpret_cast<const float2*>(xrow + r * D + k);
                    ull x0 = pack2(xv.x, xv.x);
                    ull x1 = pack2(xv.y, xv.y);
                    a[r * 2]     = fma2(x0, w0.x, a[r * 2]);
                    a[r * 2 + 1] = fma2(x0, w0.y, a[r * 2 + 1]);
                    a[r * 2]     = fma2(x1, w1.x, a[r * 2]);
                    a[r * 2 + 1] = fma2(x1, w1.y, a[r * 2 + 1]);
                }
            }

            #pragma unroll
            for (int r = 0; r < 8; r++) {
                int vrow = row0 + teamR * 8 + r;
                if (alane && vrow < V) {
                    float v0, v1, v2, v3;
                    unpack2(a[r * 2], v0, v1);
                    unpack2(a[r * 2 + 1], v2, v3);
                    *reinterpret_cast<float4*>(out + (size_t)vrow * D + jg) =
                        make_float4(v0 + b0[0], v1 + b0[1], v2 + b0[2], v3 + b0[3]);
                }
            }
        }
    }
    grid_bar();

    // ---------------- phase 5: gather (warp-per-vertex, MLP-batched) + BN ----
    {
        float sS[8], sQ[8];
        #pragma unroll
        for (int c = 0; c < 8; c++) { sS[c] = 0.f; sQ[c] = 0.f; }

        for (;;) {
            int t;
            if (lane == 0) t = atomicAdd(&g_ticket2, 1);
            t = __shfl_sync(0xffffffffu, t, 0);
            int v0 = t * 8;
            if (v0 >= V) break;
            int vend = (v0 + 8 < V) ? v0 + 8 : V;
            for (int v = v0; v < vend; v++) {
                int e0 = g_off[v], e1 = g_off[v + 1];
                size_t ob = (size_t)v * D + j0;
                float4 p0 = *reinterpret_cast<const float4*>(out + ob);
                float4 p1 = *reinterpret_cast<const float4*>(out + ob + 4);
                float acc[8] = {p0.x, p0.y, p0.z, p0.w, p1.x, p1.y, p1.z, p1.w};
                for (int bse = e0; bse < e1; bse += 32) {
                    int n = e1 - bse; if (n > 32) n = 32;
                    float2 ed = (bse + lane < e1) ? g_sedge[bse + lane]
                                                  : make_float2(0.f, 0.f);
                    int rowm = __float_as_int(ed.x);
                    int j = 0;
                    for (; j + 4 <= n; j += 4) {
                        int r0 = __shfl_sync(0xffffffffu, rowm, j);
                        int r1 = __shfl_sync(0xffffffffu, rowm, j + 1);
                        int r2 = __shfl_sync(0xffffffffu, rowm, j + 2);
                        int r3 = __shfl_sync(0xffffffffu, rowm, j + 3);
                        float n0 = __shfl_sync(0xffffffffu, ed.y, j);
                        float n1 = __shfl_sync(0xffffffffu, ed.y, j + 1);
                        float n2 = __shfl_sync(0xffffffffu, ed.y, j + 2);
                        float n3 = __shfl_sync(0xffffffffu, ed.y, j + 3);
                        const float4* q0 = reinterpret_cast<const float4*>(g_Mtab + r0 * D + j0);
                        const float4* q1 = reinterpret_cast<const float4*>(g_Mtab + r1 * D + j0);
                        const float4* q2 = reinterpret_cast<const float4*>(g_Mtab + r2 * D + j0);
                        const float4* q3 = reinterpret_cast<const float4*>(g_Mtab + r3 * D + j0);
                        float4 a0 = q0[0], b0v = q0[1];
                        float4 a1 = q1[0], b1v = q1[1];
                        float4 a2 = q2[0], b2v = q2[1];
                        float4 a3 = q3[0], b3v = q3[1];
                        acc[0] = fmaf(n0, a0.x, acc[0]); acc[1] = fmaf(n0, a0.y, acc[1]);
                        acc[2] = fmaf(n0, a0.z, acc[2]); acc[3] = fmaf(n0, a0.w, acc[3]);
                        acc[4] = fmaf(n0, b0v.x, acc[4]); acc[5] = fmaf(n0, b0v.y, acc[5]);
                        acc[6] = fmaf(n0, b0v.z, acc[6]); acc[7] = fmaf(n0, b0v.w, acc[7]);
                        acc[0] = fmaf(n1, a1.x, acc[0]); acc[1] = fmaf(n1, a1.y, acc[1]);
                        acc[2] = fmaf(n1, a1.z, acc[2]); acc[3] = fmaf(n1, a1.w, acc[3]);
                        acc[4] = fmaf(n1, b1v.x, acc[4]); acc[5] = fmaf(n1, b1v.y, acc[5]);
                        acc[6] = fmaf(n1, b1v.z, acc[6]); acc[7] = fmaf(n1, b1v.w, acc[7]);
                        acc[0] = fmaf(n2, a2.x, acc[0]); acc[1] = fmaf(n2, a2.y, acc[1]);
                        acc[2] = fmaf(n2, a2.z, acc[2]); acc[3] = fmaf(n2, a2.w, acc[3]);
                        acc[4] = fmaf(n2, b2v.x, acc[4]); acc[5] = fmaf(n2, b2v.y, acc[5]);
                        acc[6] = fmaf(n2, b2v.z, acc[6]); acc[7] = fmaf(n2, b2v.w, acc[7]);
                        acc[0] = fmaf(n3, a3.x, acc[0]); acc[1] = fmaf(n3, a3.y, acc[1]);
                        acc[2] = fmaf(n3, a3.z, acc[2]); acc[3] = fmaf(n3, a3.w, acc[3]);
                        acc[4] = fmaf(n3, b3v.x, acc[4]); acc[5] = fmaf(n3, b3v.y, acc[5]);
                        acc[6] = fmaf(n3, b3v.z, acc[6]); acc[7] = fmaf(n3, b3v.w, acc[7]);
                    }
                    for (; j < n; j++) {
                        int rr = __shfl_sync(0xffffffffu, rowm, j);
                        float nm = __shfl_sync(0xffffffffu, ed.y, j);
                        const float4* tp = reinterpret_cast<const float4*>(g_Mtab + rr * D + j0);
                        float4 t0 = tp[0], t1 = tp[1];
                        acc[0] = fmaf(nm, t0.x, acc[0]); acc[1] = fmaf(nm, t0.y, acc[1]);
                        acc[2] = fmaf(nm, t0.z, acc[2]); acc[3] = fmaf(nm, t0.w, acc[3]);
                        acc[4] = fmaf(nm, t1.x, acc[4]); acc[5] = fmaf(nm, t1.y, acc[5]);
                        acc[6] = fmaf(nm, t1.z, acc[6]); acc[7] = fmaf(nm, t1.w, acc[7]);
                    }
                }
                if (alane) {
                    *reinterpret_cast<float4*>(out + ob) =
                        make_float4(acc[0], acc[1], acc[2], acc[3]);
                    *reinterpret_cast<float4*>(out + ob + 4) =
                        make_float4(acc[4], acc[5], acc[6], acc[7]);
                    #pragma unroll
                    for (int c = 0; c < 8; c++) {
                        sS[c] += acc[c];
                        sQ[c] += acc[c] * acc[c];
                    }
                }
            }
        }

        // CTA reduce -> global atomics (warp w lanes cg<25 cover all 200 cols)
        __syncthreads();
        if (alane) {
            #pragma unroll
            for (int c = 0; c < 8; c++) dynF[team * D + j0 + c] = sS[c];
        }
        __syncthreads();
        if (tid < D) {
            float t = 0.f;
            #pragma unroll
            for (int w = 0; w < 16; w++) t += dynF[w * D + tid];
            atomicAdd(&g_sum[tid], t);
        }
        __syncthreads();
        if (alane) {
            #pragma unroll
            for (int c = 0; c < 8; c++) dynF[team * D + j0 + c] = sQ[c];
        }
        __syncthreads();
        if (tid < D) {
            float t = 0.f;
            #pragma unroll
            for (int w = 0; w < 16; w++) t += dynF[w * D + tid];
            atomicAdd(&g_sumsq[tid], t);
        }
    }
    grid_bar();

    // ---------------- phase 6: BN normalize ----------------
    {
        float invV = 1.f / (float)V;
        if (tid < D) {
            float mean = g_sum[tid] * invV;
            float var = g_sumsq[tid] * invV - mean * mean;
            float sc = bn_w[tid] * rsqrtf(var + 1e-5f);
            rs[tid] = sc;
            fred[tid] = bn_b[tid] - mean * sc;
        }
        __syncthreads();
        int r0 = cta * CHUNK;
        for (int i = tid; i < CHUNK * 50; i += THREADS) {
            int r = r0 + i / 50;
            if (r < V) {
                int c4 = (i % 50) * 4;
                float4* p = reinterpret_cast<float4*>(out + (size_t)r * D + c4);
                float4 v = *p;
                v.x = v.x * rs[c4]     + fred[c4];
                v.y = v.y * rs[c4 + 1] + fred[c4 + 1];
                v.z = v.z * rs[c4 + 2] + fred[c4 + 2];
                v.w = v.w * rs[c4 + 3] + fred[c4 + 3];
                *p = v;
            }
        }
    }
}

// ============================================================================
extern "C" void kernel_launch(void* const* d_in, const int* in_sizes, int n_in,
                              void* d_out, int out_size) {
    const float* x         = (const float*)d_in[0];
    const float* rel_repr  = (const float*)d_in[1];
    const float* edge_norm = (const float*)d_in[2];
    const float* in_w      = (const float*)d_in[3];
    const float* out_w     = (const float*)d_in[4];
    const float* loop_w    = (const float*)d_in[5];
    const float* w_rel     = (const float*)d_in[6];
    const float* loop_rel  = (const float*)d_in[7];
    const float* bias      = (const float*)d_in[8];
    const float* bn_w      = (const float*)d_in[9];
    const float* bn_b      = (const float*)d_in[10];
    const int*   edge_type = (const int*)d_in[11];
    const int*   dst       = (const int*)d_in[12];
    float* out = (float*)d_out;

    int V = in_sizes[0] / D;   // 100000
    int E = in_sizes[2];       // 1000000

    size_t smem = (size_t)(D * D + TILE * D) * sizeof(float);   // 211,200 B
    cudaFuncSetAttribute(mega_kernel,
                         cudaFuncAttributeMaxDynamicSharedMemorySize, (int)smem);

    mega_kernel<<<NCTA, THREADS, smem>>>(x, rel_repr, edge_norm, in_w, out_w,
                                         loop_w, w_rel, loop_rel, bias, bn_w,
                                         bn_b, edge_type, dst, out, V, E);
}

// round 8
// speedup vs baseline: 3.5277x; 1.0014x over previous
#include <cuda_runtime.h>
#include <cstdint>

#define D 200
#define NREL 474
#define NTAB 948
#define VMAX 100000
#define EMAX 1000000
#define THREADS 512
#define NCTA 148
#define TILE 64            // rows per tile: 8 row-groups x 8 rows
#define CHUNK 676          // ceil(VMAX/NCTA)

typedef unsigned long long ull;

// ---- device scratch (no cudaMalloc allowed) ----
__device__ __align__(16) float g_Mtab[NTAB * D];
__device__ __align__(16) float g_Weff[D * D];
__device__ __align__(16) float2 g_sedge[EMAX];
__device__ int g_cnt[VMAX];
__device__ int g_off[VMAX + 1];
__device__ int g_cursor[VMAX];
__device__ int g_bsum[NCTA];
__device__ int g_boff[NCTA];
__device__ float g_sum[D], g_sumsq[D];
__device__ unsigned g_barGen, g_barCnt;
__device__ int g_ticket, g_ticket2;

// ---- packed f32x2 ----
__device__ __forceinline__ ull fma2(ull a, ull b, ull c) {
    ull d;
    asm("fma.rn.f32x2 %0, %1, %2, %3;" : "=l"(d) : "l"(a), "l"(b), "l"(c));
    return d;
}
__device__ __forceinline__ ull pack2(float lo, float hi) {
    ull d;
    asm("mov.b64 %0, {%1, %2};" : "=l"(d) : "f"(lo), "f"(hi));
    return d;
}
__device__ __forceinline__ void unpack2(ull v, float& lo, float& hi) {
    asm("mov.b64 {%0, %1}, %2;" : "=f"(lo), "=f"(hi) : "l"(v));
}

// ---- generation grid barrier (all 148 CTAs co-resident) ----
__device__ __forceinline__ void grid_bar() {
    __syncthreads();
    if (threadIdx.x == 0) {
        unsigned gen = *(volatile unsigned*)&g_barGen;
        __threadfence();
        if (atomicAdd(&g_barCnt, 1u) == NCTA - 1) {
            g_barCnt = 0;
            __threadfence();
            atomicExch(&g_barGen, gen + 1);
        } else {
            while (*(volatile unsigned*)&g_barGen == gen) __nanosleep(32);
        }
    }
    __syncthreads();
    __threadfence();   // gpu-scope: flush L1D -> no stale lines across phases
}

// ============================================================================
__global__ void __launch_bounds__(THREADS, 1)
mega_kernel(const float* __restrict__ x,
            const float* __restrict__ rel_repr,
            const float* __restrict__ edge_norm,
            const float* __restrict__ in_w,
            const float* __restrict__ out_w,
            const float* __restrict__ loop_w,
            const float* __restrict__ w_rel,
            const float* __restrict__ loop_rel,
            const float* __restrict__ bias,
            const float* __restrict__ bn_w,
            const float* __restrict__ bn_b,
            const int* __restrict__ edge_type,
            const int* __restrict__ dst,
            float* __restrict__ out, int V, int E) {
    extern __shared__ float dynF[];          // [0,D*D): W ; then TILE*D xs
    float* xsF = dynF + D * D;
    __shared__ int   ism[THREADS];
    __shared__ int   s2[256];
    __shared__ float fred[THREADS];
    __shared__ float rs[D];
    __shared__ int   ibroad;

    const int tid  = threadIdx.x;
    const int cta  = blockIdx.x;
    const int lane = tid & 31;
    const int team = tid >> 5;               // 16 warps
    const int cg   = (lane < 25) ? lane : 24;
    const bool alane = (lane < 25);
    const int halfE = E / 2;
    float* rel_out = out + (size_t)V * D;

    // GEMM column mapping: warp pair splits columns
    const int teamR   = team >> 1;           // 8 row groups (8 rows each)
    const int colhalf = team & 1;            // 2 column halves of 100
    const int jg      = colhalf * 100 + cg * 4;   // 4 cols per lane (GEMM)
    // gather column mapping: 8 cols per lane
    const int j0 = cg * 8;

    // ---------------- phase 0: zero ----------------
    for (int i = cta * THREADS + tid; i < V; i += NCTA * THREADS) g_cnt[i] = 0;
    if (cta == 0) {
        if (tid < D) { g_sum[tid] = 0.f; g_sumsq[tid] = 0.f; }
        if (tid == 0) { g_ticket = 0; g_ticket2 = 0; }
    }
    grid_bar();

    // ---------------- phase 1: histogram of dst ----------------
    for (int e = cta * THREADS + tid; e < E; e += NCTA * THREADS)
        atomicAdd(&g_cnt[dst[e]], 1);
    grid_bar();

    // ---------------- phase 2: scan ----------------
    const int c0 = cta * CHUNK;
    int i0 = c0 + tid * 2;
    bool v0ok = (tid * 2 < CHUNK) && (i0 < V);
    bool v1ok = (tid * 2 + 1 < CHUNK) && (i0 + 1 < V);
    int ca = v0ok ? g_cnt[i0] : 0;
    int cb = v1ok ? g_cnt[i0 + 1] : 0;
    int local = ca + cb;
    ism[tid] = local;
    __syncthreads();
    for (int s = 1; s < THREADS; s <<= 1) {
        int u = (tid >= s) ? ism[tid - s] : 0;
        __syncthreads();
        ism[tid] += u;
        __syncthreads();
    }
    if (tid == THREADS - 1) g_bsum[cta] = ism[THREADS - 1];
    grid_bar();

    if (cta == 0) {
        int v = (tid < NCTA) ? g_bsum[tid] : 0;
        if (tid < 256) s2[tid] = v;
        __syncthreads();
        for (int s = 1; s < 256; s <<= 1) {
            int u = (tid >= s && tid < 256) ? s2[tid - s] : 0;
            __syncthreads();
            if (tid < 256) s2[tid] += u;
            __syncthreads();
        }
        if (tid < NCTA) g_boff[tid] = s2[tid] - v;
        if (tid == 0) g_off[V] = E;
    }
    grid_bar();

    {
        int base = ism[tid] - local + g_boff[cta];
        if (v0ok) { g_off[i0] = base;          g_cursor[i0] = base; }
        if (v1ok) { g_off[i0 + 1] = base + ca; g_cursor[i0 + 1] = base + ca; }
    }
    grid_bar();

    // ---------------- phase 3: sortscatter + prep ----------------
    for (int e = cta * THREADS + tid; e < E; e += NCTA * THREADS) {
        int v = dst[e];
        int row = edge_type[e] + ((e >= halfE) ? NREL : 0);
        int pos = atomicAdd(&g_cursor[v], 1);
        g_sedge[pos] = make_float2(__int_as_float(row), edge_norm[e]);
    }

    {   // prep: 4 tasks per weight sweep (scratch = xsF)
        const int nb = (NREL + 3) / 4;       // 119
        const int totalB = nb * 2 + (D / 4) + nb;
        for (int bb = cta; bb < totalB; bb += NCTA) {
            if (bb < 2 * nb) {
                int hh = bb / nb;
                int b4 = (bb % nb) * 4;
                const float* W = hh ? out_w : in_w;
                for (int i = tid; i < 4 * D; i += THREADS) {
                    int j = i / D, k = i - j * D;
                    int t = b4 + j;
                    xsF[i] = (t < NREL) ? rel_repr[t * D + k] : 0.f;
                }
                __syncthreads();
                float acc[4] = {0.f, 0.f, 0.f, 0.f};
                if (tid < D) {
                    for (int k = 0; k < D; k++) {
                        float wv = W[k * D + tid];
                        #pragma unroll
                        for (int j = 0; j < 4; j++)
                            acc[j] = fmaf(xsF[j * D + k], wv, acc[j]);
                    }
                }
                float ee[4], inv[4];
                #pragma unroll
                for (int j = 0; j < 4; j++) {
                    fred[tid] = (tid < D) ? acc[j] : -1e30f;
                    __syncthreads();
                    for (int s = 256; s > 0; s >>= 1) {
                        if (tid < s) fred[tid] = fmaxf(fred[tid], fred[tid + s]);
                        __syncthreads();
                    }
                    float mx = fred[0];
                    __syncthreads();
                    ee[j] = (tid < D) ? expf(acc[j] - mx) : 0.f;
                    fred[tid] = ee[j];
                    __syncthreads();
                    for (int s = 256; s > 0; s >>= 1) {
                        if (tid < s) fred[tid] += fred[tid + s];
                        __syncthreads();
                    }
                    inv[j] = 1.f / (fred[0] * 3.f);
                    __syncthreads();
                }
                if (tid < D) {
                    #pragma unroll
                    for (int j = 0; j < 4; j++) {
                        int t = b4 + j;
                        if (t < NREL)
                            g_Mtab[(hh * NREL + t) * D + tid] = ee[j] * inv[j];
                    }
                }
                __syncthreads();
            } else if (bb < 2 * nb + D / 4) {
                int kk0 = (bb - 2 * nb) * 4;
                if (tid < D) rs[tid] = loop_rel[tid];
                __syncthreads();
                if (tid < D) {
                    float acc[4] = {0.f, 0.f, 0.f, 0.f};
                    for (int m = 0; m < D; m++) {
                        float wv = loop_w[m * D + tid];
                        #pragma unroll
                        for (int j = 0; j < 4; j++) {
                            int mm = m + kk0 + j;
                            if (mm >= D) mm -= D;
                            acc[j] = fmaf(rs[mm], wv, acc[j]);
                        }
                    }
                    #pragma unroll
                    for (int j = 0; j < 4; j++)
                        g_Weff[(kk0 + j) * D + tid] = acc[j] * (1.f / 3.f);
                }
                __syncthreads();
            } else {
                int b4 = (bb - 2 * nb - D / 4) * 4;
                for (int i = tid; i < 4 * D; i += THREADS) {
                    int j = i / D, k = i - j * D;
                    int t = b4 + j;
                    xsF[i] = (t < NREL) ? rel_repr[t * D + k] : 0.f;
                }
                __syncthreads();
                if (tid < D) {
                    float acc[4] = {0.f, 0.f, 0.f, 0.f};
                    for (int k = 0; k < D; k++) {
                        float wv = w_rel[k * D + tid];
                        #pragma unroll
                        for (int j = 0; j < 4; j++)
                            acc[j] = fmaf(xsF[j * D + k], wv, acc[j]);
                    }
                    #pragma unroll
                    for (int j = 0; j < 4; j++)
                        if (b4 + j < NREL) rel_out[(b4 + j) * D + tid] = acc[j];
                }
                __syncthreads();
            }
        }
    }
    grid_bar();

    // ---------------- phase 4: GEMM out = x@Weff + bias ----------------
    // W resident in smem. 8 rows x 4 cols per thread, FFMA2, k unrolled by 4
    // with float4 x broadcasts (halved x wavefronts -> fma-bound).
    for (int i = tid; i < D * D; i += THREADS) dynF[i] = g_Weff[i];

    {
        float b0[4];
        #pragma unroll
        for (int c = 0; c < 4; c++) b0[c] = bias[jg + c];

        const int ntiles = (V + TILE - 1) / TILE;
        for (;;) {
            __syncthreads();
            if (tid == 0) ibroad = atomicAdd(&g_ticket, 1);
            __syncthreads();
            int tile = ibroad;
            if (tile >= ntiles) break;
            int row0 = tile * TILE;

            for (int i = tid; i < TILE * 50; i += THREADS) {
                int r = row0 + i / 50;
                float4 v = (r < V)
                    ? reinterpret_cast<const float4*>(x)[(size_t)r * 50 + (i % 50)]
                    : make_float4(0.f, 0.f, 0.f, 0.f);
                reinterpret_cast<float4*>(xsF)[i] = v;
            }
            __syncthreads();

            ull a[16];                         // 8 rows x 2 fma2 (4 cols)
            #pragma unroll
            for (int i = 0; i < 16; i++) a[i] = 0ull;
            const float* xrow = xsF + teamR * 8 * D;
            #pragma unroll 2
            for (int k = 0; k < D; k += 4) {
                ulonglong2 w0 = *reinterpret_cast<const ulonglong2*>(dynF + k * D + jg);
                ulonglong2 w1 = *reinterpret_cast<const ulonglong2*>(dynF + (k + 1) * D + jg);
                ulonglong2 w2 = *reinterpret_cast<const ulonglong2*>(dynF + (k + 2) * D + jg);
                ulonglong2 w3 = *reinterpret_cast<const ulonglong2*>(dynF + (k + 3) * D + jg);
                #pragma unroll
                for (int r = 0; r < 8; r++) {
                    float4 xv = *reinterpret_cast<const float4*>(xrow + r * D + k);
                    ull x0 = pack2(xv.x, xv.x);
                    ull x1 = pack2(xv.y, xv.y);
                    ull x2 = pack2(xv.z, xv.z);
                    ull x3 = pack2(xv.w, xv.w);
                    a[r * 2]     = fma2(x0, w0.x, a[r * 2]);
                    a[r * 2 + 1] = fma2(x0, w0.y, a[r * 2 + 1]);
                    a[r * 2]     = fma2(x1, w1.x, a[r * 2]);
                    a[r * 2 + 1] = fma2(x1, w1.y, a[r * 2 + 1]);
                    a[r * 2]     = fma2(x2, w2.x, a[r * 2]);
                    a[r * 2 + 1] = fma2(x2, w2.y, a[r * 2 + 1]);
                    a[r * 2]     = fma2(x3, w3.x, a[r * 2]);
                    a[r * 2 + 1] = fma2(x3, w3.y, a[r * 2 + 1]);
                }
            }

            #pragma unroll
            for (int r = 0; r < 8; r++) {
                int vrow = row0 + teamR * 8 + r;
                if (alane && vrow < V) {
                    float v0, v1, v2, v3;
                    unpack2(a[r * 2], v0, v1);
                    unpack2(a[r * 2 + 1], v2, v3);
                    *reinterpret_cast<float4*>(out + (size_t)vrow * D + jg) =
                        make_float4(v0 + b0[0], v1 + b0[1], v2 + b0[2], v3 + b0[3]);
                }
            }
        }
    }
    grid_bar();

    // ---------------- phase 5: gather (2-vertex merged windows) + BN --------
    {
        float sS[8], sQ[8];
        #pragma unroll
        for (int c = 0; c < 8; c++) { sS[c] = 0.f; sQ[c] = 0.f; }

        for (;;) {
            int t;
            if (lane == 0) t = atomicAdd(&g_ticket2, 1);
            t = __shfl_sync(0xffffffffu, t, 0);
            int v0 = t * 8;
            if (v0 >= V) break;
            int vend = (v0 + 8 < V) ? v0 + 8 : V;
            for (int v = v0; v < vend; v += 2) {
                bool hasB = (v + 1 < vend);
                int e0 = g_off[v];
                int e1 = g_off[v + 1];
                int e2 = hasB ? g_off[v + 2] : e1;

                // prefetch base values (overlaps edge processing)
                size_t obA = (size_t)v * D + j0;
                float4 pA0 = *reinterpret_cast<const float4*>(out + obA);
                float4 pA1 = *reinterpret_cast<const float4*>(out + obA + 4);
                float4 pB0 = make_float4(0.f, 0.f, 0.f, 0.f), pB1 = pB0;
                size_t obB = (size_t)(v + 1) * D + j0;
                if (hasB) {
                    pB0 = *reinterpret_cast<const float4*>(out + obB);
                    pB1 = *reinterpret_cast<const float4*>(out + obB + 4);
                }

                float accA[8] = {0.f,0.f,0.f,0.f,0.f,0.f,0.f,0.f};
                float accB[8] = {0.f,0.f,0.f,0.f,0.f,0.f,0.f,0.f};

                for (int bse = e0; bse < e2; bse += 32) {
                    int n = e2 - bse; if (n > 32) n = 32;
                    float2 ed = (bse + lane < e2) ? g_sedge[bse + lane]
                                                  : make_float2(0.f, 0.f);
                    int rowm = __float_as_int(ed.x);
                    int nA = e1 - bse;
                    if (nA < 0) nA = 0;
                    if (nA > n) nA = n;

                    // segment A -> accA, segment B -> accB (uniform loops)
                    #pragma unroll 1
                    for (int seg = 0; seg < 2; seg++) {
                        int js = seg ? nA : 0;
                        int je = seg ? n : nA;
                        float* acc = seg ? accB : accA;
                        int j = js;
                        for (; j + 4 <= je; j += 4) {
                            int r0 = __shfl_sync(0xffffffffu, rowm, j);
                            int r1 = __shfl_sync(0xffffffffu, rowm, j + 1);
                            int r2 = __shfl_sync(0xffffffffu, rowm, j + 2);
                            int r3 = __shfl_sync(0xffffffffu, rowm, j + 3);
                            float n0 = __shfl_sync(0xffffffffu, ed.y, j);
                            float n1 = __shfl_sync(0xffffffffu, ed.y, j + 1);
                            float n2 = __shfl_sync(0xffffffffu, ed.y, j + 2);
                            float n3 = __shfl_sync(0xffffffffu, ed.y, j + 3);
                            const float4* q0 = reinterpret_cast<const float4*>(g_Mtab + r0 * D + j0);
                            const float4* q1 = reinterpret_cast<const float4*>(g_Mtab + r1 * D + j0);
                            const float4* q2 = reinterpret_cast<const float4*>(g_Mtab + r2 * D + j0);
                            const float4* q3 = reinterpret_cast<const float4*>(g_Mtab + r3 * D + j0);
                            float4 a0 = q0[0], c0 = q0[1];
                            float4 a1 = q1[0], c1 = q1[1];
                            float4 a2 = q2[0], c2 = q2[1];
                            float4 a3 = q3[0], c3 = q3[1];
                            acc[0] = fmaf(n0, a0.x, acc[0]); acc[1] = fmaf(n0, a0.y, acc[1]);
                            acc[2] = fmaf(n0, a0.z, acc[2]); acc[3] = fmaf(n0, a0.w, acc[3]);
                            acc[4] = fmaf(n0, c0.x, acc[4]); acc[5] = fmaf(n0, c0.y, acc[5]);
                            acc[6] = fmaf(n0, c0.z, acc[6]); acc[7] = fmaf(n0, c0.w, acc[7]);
                            acc[0] = fmaf(n1, a1.x, acc[0]); acc[1] = fmaf(n1, a1.y, acc[1]);
                            acc[2] = fmaf(n1, a1.z, acc[2]); acc[3] = fmaf(n1, a1.w, acc[3]);
                            acc[4] = fmaf(n1, c1.x, acc[4]); acc[5] = fmaf(n1, c1.y, acc[5]);
                            acc[6] = fmaf(n1, c1.z, acc[6]); acc[7] = fmaf(n1, c1.w, acc[7]);
                            acc[0] = fmaf(n2, a2.x, acc[0]); acc[1] = fmaf(n2, a2.y, acc[1]);
                            acc[2] = fmaf(n2, a2.z, acc[2]); acc[3] = fmaf(n2, a2.w, acc[3]);
                            acc[4] = fmaf(n2, c2.x, acc[4]); acc[5] = fmaf(n2, c2.y, acc[5]);
                            acc[6] = fmaf(n2, c2.z, acc[6]); acc[7] = fmaf(n2, c2.w, acc[7]);
                            acc[0] = fmaf(n3, a3.x, acc[0]); acc[1] = fmaf(n3, a3.y, acc[1]);
                            acc[2] = fmaf(n3, a3.z, acc[2]); acc[3] = fmaf(n3, a3.w, acc[3]);
                            acc[4] = fmaf(n3, c3.x, acc[4]); acc[5] = fmaf(n3, c3.y, acc[5]);
                            acc[6] = fmaf(n3, c3.z, acc[6]); acc[7] = fmaf(n3, c3.w, acc[7]);
                        }
                        for (; j < je; j++) {
                            int rr = __shfl_sync(0xffffffffu, rowm, j);
                            float nm = __shfl_sync(0xffffffffu, ed.y, j);
                            const float4* tp = reinterpret_cast<const float4*>(g_Mtab + rr * D + j0);
                            float4 t0 = tp[0], t1 = tp[1];
                            acc[0] = fmaf(nm, t0.x, acc[0]); acc[1] = fmaf(nm, t0.y, acc[1]);
                            acc[2] = fmaf(nm, t0.z, acc[2]); acc[3] = fmaf(nm, t0.w, acc[3]);
                            acc[4] = fmaf(nm, t1.x, acc[4]); acc[5] = fmaf(nm, t1.y, acc[5]);
                            acc[6] = fmaf(nm, t1.z, acc[6]); acc[7] = fmaf(nm, t1.w, acc[7]);
                        }
                    }
                }

                if (alane) {
                    accA[0] += pA0.x; accA[1] += pA0.y; accA[2] += pA0.z; accA[3] += pA0.w;
                    accA[4] += pA1.x; accA[5] += pA1.y; accA[6] += pA1.z; accA[7] += pA1.w;
                    *reinterpret_cast<float4*>(out + obA) =
                        make_float4(accA[0], accA[1], accA[2], accA[3]);
                    *reinterpret_cast<float4*>(out + obA + 4) =
                        make_float4(accA[4], accA[5], accA[6], accA[7]);
                    #pragma unroll
                    for (int c = 0; c < 8; c++) {
                        sS[c] += accA[c];
                        sQ[c] += accA[c] * accA[c];
                    }
                    if (hasB) {
                        accB[0] += pB0.x; accB[1] += pB0.y; accB[2] += pB0.z; accB[3] += pB0.w;
                        accB[4] += pB1.x; accB[5] += pB1.y; accB[6] += pB1.z; accB[7] += pB1.w;
                        *reinterpret_cast<float4*>(out + obB) =
                            make_float4(accB[0], accB[1], accB[2], accB[3]);
                        *reinterpret_cast<float4*>(out + obB + 4) =
                            make_float4(accB[4], accB[5], accB[6], accB[7]);
                        #pragma unroll
                        for (int c = 0; c < 8; c++) {
                            sS[c] += accB[c];
                            sQ[c] += accB[c] * accB[c];
                        }
                    }
                }
            }
        }

        // CTA reduce -> global atomics
        __syncthreads();
        if (alane) {
            #pragma unroll
            for (int c = 0; c < 8; c++) dynF[team * D + j0 + c] = sS[c];
        }
        __syncthreads();
        if (tid < D) {
            float t = 0.f;
            #pragma unroll
            for (int w = 0; w < 16; w++) t += dynF[w * D + tid];
            atomicAdd(&g_sum[tid], t);
        }
        __syncthreads();
        if (alane) {
            #pragma unroll
            for (int c = 0; c < 8; c++) dynF[team * D + j0 + c] = sQ[c];
        }
        __syncthreads();
        if (tid < D) {
            float t = 0.f;
            #pragma unroll
            for (int w = 0; w < 16; w++) t += dynF[w * D + tid];
            atomicAdd(&g_sumsq[tid], t);
        }
    }
    grid_bar();

    // ---------------- phase 6: BN normalize ----------------
    {
        float invV = 1.f / (float)V;
        if (tid < D) {
            float mean = g_sum[tid] * invV;
            float var = g_sumsq[tid] * invV - mean * mean;
            float sc = bn_w[tid] * rsqrtf(var + 1e-5f);
            rs[tid] = sc;
            fred[tid] = bn_b[tid] - mean * sc;
        }
        __syncthreads();
        int r0 = cta * CHUNK;
        for (int i = tid; i < CHUNK * 50; i += THREADS) {
            int r = r0 + i / 50;
            if (r < V) {
                int c4 = (i % 50) * 4;
                float4* p = reinterpret_cast<float4*>(out + (size_t)r * D + c4);
                float4 v = *p;
                v.x = v.x * rs[c4]     + fred[c4];
                v.y = v.y * rs[c4 + 1] + fred[c4 + 1];
                v.z = v.z * rs[c4 + 2] + fred[c4 + 2];
                v.w = v.w * rs[c4 + 3] + fred[c4 + 3];
                *p = v;
            }
        }
    }
}

// ============================================================================
extern "C" void kernel_launch(void* const* d_in, const int* in_sizes, int n_in,
                              void* d_out, int out_size) {
    const float* x         = (const float*)d_in[0];
    const float* rel_repr  = (const float*)d_in[1];
    const float* edge_norm = (const float*)d_in[2];
    const float* in_w      = (const float*)d_in[3];
    const float* out_w     = (const float*)d_in[4];
    const float* loop_w    = (const float*)d_in[5];
    const float* w_rel     = (const float*)d_in[6];
    const float* loop_rel  = (const float*)d_in[7];
    const float* bias      = (const float*)d_in[8];
    const float* bn_w      = (const float*)d_in[9];
    const float* bn_b      = (const float*)d_in[10];
    const int*   edge_type = (const int*)d_in[11];
    const int*   dst       = (const int*)d_in[12];
    float* out = (float*)d_out;

    int V = in_sizes[0] / D;   // 100000
    int E = in_sizes[2];       // 1000000

    size_t smem = (size_t)(D * D + TILE * D) * sizeof(float);   // 211,200 B
    cudaFuncSetAttribute(mega_kernel,
                         cudaFuncAttributeMaxDynamicSharedMemorySize, (int)smem);

    mega_kernel<<<NCTA, THREADS, smem>>>(x, rel_repr, edge_norm, in_w, out_w,
                                         loop_w, w_rel, loop_rel, bias, bn_w,
                                         bn_b, edge_type, dst, out, V, E);
}

// round 11
// speedup vs baseline: 3.6174x; 1.0254x over previous
#include <cuda_runtime.h>
#include <cstdint>

#define D 200
#define NREL 474
#define NTAB 948
#define VMAX 100000
#define EMAX 1000000
#define THREADS 512
#define NCTA 148
#define CHUNK 676          // ceil(VMAX/NCTA)

typedef unsigned long long ull;

// ---- device scratch (no cudaMalloc allowed) ----
__device__ __align__(16) float g_Mtab[NTAB * D];
__device__ __align__(16) float g_Weff[D * D];
__device__ __align__(16) float2 g_sedge[EMAX];
__device__ int g_cnt[VMAX];
__device__ int g_off[VMAX + 1];
__device__ int g_cursor[VMAX];
__device__ int g_bsum[NCTA];
__device__ int g_boff[NCTA];
__device__ float g_sum[D], g_sumsq[D];
__device__ unsigned g_barGen, g_barCnt;
__device__ int g_ticket;

// ---- packed f32x2 ----
__device__ __forceinline__ ull fma2(ull a, ull b, ull c) {
    ull d;
    asm("fma.rn.f32x2 %0, %1, %2, %3;" : "=l"(d) : "l"(a), "l"(b), "l"(c));
    return d;
}
__device__ __forceinline__ ull pack2(float lo, float hi) {
    ull d;
    asm("mov.b64 %0, {%1, %2};" : "=l"(d) : "f"(lo), "f"(hi));
    return d;
}
__device__ __forceinline__ void unpack2(ull v, float& lo, float& hi) {
    asm("mov.b64 {%0, %1}, %2;" : "=f"(lo), "=f"(hi) : "l"(v));
}

// ---- generation grid barrier (all 148 CTAs co-resident) ----
__device__ __forceinline__ void grid_bar() {
    __syncthreads();
    if (threadIdx.x == 0) {
        unsigned gen = *(volatile unsigned*)&g_barGen;
        __threadfence();
        if (atomicAdd(&g_barCnt, 1u) == NCTA - 1) {
            g_barCnt = 0;
            __threadfence();
            atomicExch(&g_barGen, gen + 1);
        } else {
            while (*(volatile unsigned*)&g_barGen == gen) __nanosleep(32);
        }
    }
    __syncthreads();
    __threadfence();   // gpu-scope: flush L1D -> no stale lines across phases
}

// ============================================================================
__global__ void __launch_bounds__(THREADS, 1)
mega_kernel(const float* __restrict__ x,
            const float* __restrict__ rel_repr,
            const float* __restrict__ edge_norm,
            const float* __restrict__ in_w,
            const float* __restrict__ out_w,
            const float* __restrict__ loop_w,
            const float* __restrict__ w_rel,
            const float* __restrict__ loop_rel,
            const float* __restrict__ bias,
            const float* __restrict__ bn_w,
            const float* __restrict__ bn_b,
            const int* __restrict__ edge_type,
            const int* __restrict__ dst,
            float* __restrict__ out, int V, int E) {
    extern __shared__ float dynF[];          // [0,D*D): W ; [D*D, D*D+4*D): prep scratch
    float* xsF = dynF + D * D;
    __shared__ int   ism[THREADS];
    __shared__ int   s2[256];
    __shared__ float fred[THREADS];
    __shared__ float rs[D];

    const int tid  = threadIdx.x;
    const int cta  = blockIdx.x;
    const int lane = tid & 31;
    const int team = tid >> 5;               // 16 warps
    const int cg   = (lane < 25) ? lane : 24;
    const bool alane = (lane < 25);
    const int j0   = cg * 8;                 // 8 cols per lane
    const int halfE = E / 2;
    float* rel_out = out + (size_t)V * D;

    // ---------------- phase 0: zero ----------------
    for (int i = cta * THREADS + tid; i < V; i += NCTA * THREADS) g_cnt[i] = 0;
    if (cta == 0) {
        if (tid < D) { g_sum[tid] = 0.f; g_sumsq[tid] = 0.f; }
        if (tid == 0) g_ticket = 0;
    }
    grid_bar();

    // ---------------- phase 1: histogram of dst ----------------
    for (int e = cta * THREADS + tid; e < E; e += NCTA * THREADS)
        atomicAdd(&g_cnt[dst[e]], 1);
    grid_bar();

    // ---------------- phase 2: scan ----------------
    const int c0 = cta * CHUNK;
    int i0 = c0 + tid * 2;
    bool v0ok = (tid * 2 < CHUNK) && (i0 < V);
    bool v1ok = (tid * 2 + 1 < CHUNK) && (i0 + 1 < V);
    int ca = v0ok ? g_cnt[i0] : 0;
    int cb = v1ok ? g_cnt[i0 + 1] : 0;
    int local = ca + cb;
    ism[tid] = local;
    __syncthreads();
    for (int s = 1; s < THREADS; s <<= 1) {
        int u = (tid >= s) ? ism[tid - s] : 0;
        __syncthreads();
        ism[tid] += u;
        __syncthreads();
    }
    if (tid == THREADS - 1) g_bsum[cta] = ism[THREADS - 1];
    grid_bar();

    if (cta == 0) {
        int v = (tid < NCTA) ? g_bsum[tid] : 0;
        if (tid < 256) s2[tid] = v;
        __syncthreads();
        for (int s = 1; s < 256; s <<= 1) {
            int u = (tid >= s && tid < 256) ? s2[tid - s] : 0;
            __syncthreads();
            if (tid < 256) s2[tid] += u;
            __syncthreads();
        }
        if (tid < NCTA) g_boff[tid] = s2[tid] - v;
        if (tid == 0) g_off[V] = E;
    }
    grid_bar();

    {
        int base = ism[tid] - local + g_boff[cta];
        if (v0ok) { g_off[i0] = base;          g_cursor[i0] = base; }
        if (v1ok) { g_off[i0 + 1] = base + ca; g_cursor[i0 + 1] = base + ca; }
    }
    grid_bar();

    // ---------------- phase 3: sortscatter + prep ----------------
    for (int e = cta * THREADS + tid; e < E; e += NCTA * THREADS) {
        int v = dst[e];
        int row = edge_type[e] + ((e >= halfE) ? NREL : 0);
        int pos = atomicAdd(&g_cursor[v], 1);
        g_sedge[pos] = make_float2(__int_as_float(row), edge_norm[e]);
    }

    {   // prep: 4 tasks per weight sweep (scratch = xsF)
        const int nb = (NREL + 3) / 4;       // 119
        const int totalB = nb * 2 + (D / 4) + nb;
        for (int bb = cta; bb < totalB; bb += NCTA) {
            if (bb < 2 * nb) {
                int hh = bb / nb;
                int b4 = (bb % nb) * 4;
                const float* W = hh ? out_w : in_w;
                for (int i = tid; i < 4 * D; i += THREADS) {
                    int j = i / D, k = i - j * D;
                    int t = b4 + j;
                    xsF[i] = (t < NREL) ? rel_repr[t * D + k] : 0.f;
                }
                __syncthreads();
                float acc[4] = {0.f, 0.f, 0.f, 0.f};
                if (tid < D) {
                    for (int k = 0; k < D; k++) {
                        float wv = W[k * D + tid];
                        #pragma unroll
                        for (int j = 0; j < 4; j++)
                            acc[j] = fmaf(xsF[j * D + k], wv, acc[j]);
                    }
                }
                float ee[4], inv[4];
                #pragma unroll
                for (int j = 0; j < 4; j++) {
                    fred[tid] = (tid < D) ? acc[j] : -1e30f;
                    __syncthreads();
                    for (int s = 256; s > 0; s >>= 1) {
                        if (tid < s) fred[tid] = fmaxf(fred[tid], fred[tid + s]);
                        __syncthreads();
                    }
                    float mx = fred[0];
                    __syncthreads();
                    ee[j] = (tid < D) ? expf(acc[j] - mx) : 0.f;
                    fred[tid] = ee[j];
                    __syncthreads();
                    for (int s = 256; s > 0; s >>= 1) {
                        if (tid < s) fred[tid] += fred[tid + s];
                        __syncthreads();
                    }
                    inv[j] = 1.f / (fred[0] * 3.f);
                    __syncthreads();
                }
                if (tid < D) {
                    #pragma unroll
                    for (int j = 0; j < 4; j++) {
                        int t = b4 + j;
                        if (t < NREL)
                            g_Mtab[(hh * NREL + t) * D + tid] = ee[j] * inv[j];
                    }
                }
                __syncthreads();
            } else if (bb < 2 * nb + D / 4) {
                int kk0 = (bb - 2 * nb) * 4;
                if (tid < D) rs[tid] = loop_rel[tid];
                __syncthreads();
                if (tid < D) {
                    float acc[4] = {0.f, 0.f, 0.f, 0.f};
                    for (int m = 0; m < D; m++) {
                        float wv = loop_w[m * D + tid];
                        #pragma unroll
                        for (int j = 0; j < 4; j++) {
                            int mm = m + kk0 + j;
                            if (mm >= D) mm -= D;
                            acc[j] = fmaf(rs[mm], wv, acc[j]);
                        }
                    }
                    #pragma unroll
                    for (int j = 0; j < 4; j++)
                        g_Weff[(kk0 + j) * D + tid] = acc[j] * (1.f / 3.f);
                }
                __syncthreads();
            } else {
                int b4 = (bb - 2 * nb - D / 4) * 4;
                for (int i = tid; i < 4 * D; i += THREADS) {
                    int j = i / D, k = i - j * D;
                    int t = b4 + j;
                    xsF[i] = (t < NREL) ? rel_repr[t * D + k] : 0.f;
                }
                __syncthreads();
                if (tid < D) {
                    float acc[4] = {0.f, 0.f, 0.f, 0.f};
                    for (int k = 0; k < D; k++) {
                        float wv = w_rel[k * D + tid];
                        #pragma unroll
                        for (int j = 0; j < 4; j++)
                            acc[j] = fmaf(xsF[j * D + k], wv, acc[j]);
                    }
                    #pragma unroll
                    for (int j = 0; j < 4; j++)
                        if (b4 + j < NREL) rel_out[(b4 + j) * D + tid] = acc[j];
                }
                __syncthreads();
            }
        }
    }
    grid_bar();

    // ---------------- phase 4: MERGED GEMM + gather + BN stats ----------------
    // Warp-autonomous task = 8 consecutive vertices: GEMM from smem-W /
    // broadcast-LDG x, then CSR gather of the same vertices into the same
    // accumulators, single store, BN partials. No block syncs in the loop.
    for (int i = tid; i < D * D; i += THREADS) dynF[i] = g_Weff[i];
    __syncthreads();

    {
        float b0[8];
        #pragma unroll
        for (int c = 0; c < 8; c++) b0[c] = bias[j0 + c];
        float sS[8], sQ[8];
        #pragma unroll
        for (int c = 0; c < 8; c++) { sS[c] = 0.f; sQ[c] = 0.f; }

        const float* wb = dynF + j0;
        const int ntasks = (V + 7) / 8;

        for (;;) {
            int t;
            if (lane == 0) t = atomicAdd(&g_ticket, 1);
            t = __shfl_sync(0xffffffffu, t, 0);
            if (t >= ntasks) break;
            int v0 = t * 8;

            // ---- GEMM: 8 rows x 8 cols/lane, col-paired FFMA2 ----
            ull acc[32];
            #pragma unroll
            for (int i = 0; i < 32; i++) acc[i] = 0ull;
            const float* xb = x + (size_t)v0 * D;
            #pragma unroll 2
            for (int k = 0; k < D; k += 2) {
                ulonglong2 wA0 = *reinterpret_cast<const ulonglong2*>(wb + k * D);
                ulonglong2 wB0 = *reinterpret_cast<const ulonglong2*>(wb + k * D + 4);
                ulonglong2 wA1 = *reinterpret_cast<const ulonglong2*>(wb + (k + 1) * D);
                ulonglong2 wB1 = *reinterpret_cast<const ulonglong2*>(wb + (k + 1) * D + 4);
                #pragma unroll
                for (int r = 0; r < 8; r++) {
                    float2 xv = *reinterpret_cast<const float2*>(xb + r * D + k);
                    ull x0 = pack2(xv.x, xv.x);
                    ull x1 = pack2(xv.y, xv.y);
                    acc[r * 4 + 0] = fma2(x0, wA0.x, acc[r * 4 + 0]);
                    acc[r * 4 + 1] = fma2(x0, wA0.y, acc[r * 4 + 1]);
                    acc[r * 4 + 2] = fma2(x0, wB0.x, acc[r * 4 + 2]);
                    acc[r * 4 + 3] = fma2(x0, wB0.y, acc[r * 4 + 3]);
                    acc[r * 4 + 0] = fma2(x1, wA1.x, acc[r * 4 + 0]);
                    acc[r * 4 + 1] = fma2(x1, wA1.y, acc[r * 4 + 1]);
                    acc[r * 4 + 2] = fma2(x1, wB1.x, acc[r * 4 + 2]);
                    acc[r * 4 + 3] = fma2(x1, wB1.y, acc[r * 4 + 3]);
                }
            }

            // ---- gather: edges of v0..v0+7 are contiguous in g_sedge ----
            int eend = g_off[v0 + 8];
            int ofr = (lane < 9) ? g_off[v0 + lane] : 0;
            int bse = 0, winEnd = -1;          // force first window load
            float2 edv = make_float2(0.f, 0.f);
            int rowm = 0;

            #pragma unroll
            for (int r = 0; r < 8; r++) {
                int e0 = __shfl_sync(0xffffffffu, ofr, r);
                int e1 = __shfl_sync(0xffffffffu, ofr, r + 1);
                float fa[8] = {0.f, 0.f, 0.f, 0.f, 0.f, 0.f, 0.f, 0.f};
                int e = e0;
                while (e < e1) {
                    if (e >= winEnd) {
                        bse = e;
                        edv = (bse + lane < eend) ? g_sedge[bse + lane]
                                                  : make_float2(0.f, 0.f);
                        rowm = __float_as_int(edv.x);
                        winEnd = bse + 32;
                    }
                    int lim = (e1 < winEnd) ? e1 : winEnd;
                    int j = e - bse;
                    int jend = lim - bse;
                    for (; j + 4 <= jend; j += 4) {
                        int r0 = __shfl_sync(0xffffffffu, rowm, j);
                        int r1 = __shfl_sync(0xffffffffu, rowm, j + 1);
                        int r2 = __shfl_sync(0xffffffffu, rowm, j + 2);
                        int r3 = __shfl_sync(0xffffffffu, rowm, j + 3);
                        float n0 = __shfl_sync(0xffffffffu, edv.y, j);
                        float n1 = __shfl_sync(0xffffffffu, edv.y, j + 1);
                        float n2 = __shfl_sync(0xffffffffu, edv.y, j + 2);
                        float n3 = __shfl_sync(0xffffffffu, edv.y, j + 3);
                        const float4* q0 = reinterpret_cast<const float4*>(g_Mtab + r0 * D + j0);
                        const float4* q1 = reinterpret_cast<const float4*>(g_Mtab + r1 * D + j0);
                        const float4* q2 = reinterpret_cast<const float4*>(g_Mtab + r2 * D + j0);
                        const float4* q3 = reinterpret_cast<const float4*>(g_Mtab + r3 * D + j0);
                        float4 a0 = q0[0], c0v = q0[1];
                        float4 a1 = q1[0], c1v = q1[1];
                        float4 a2 = q2[0], c2v = q2[1];
                        float4 a3 = q3[0], c3v = q3[1];
                        fa[0] = fmaf(n0, a0.x, fa[0]); fa[1] = fmaf(n0, a0.y, fa[1]);
                        fa[2] = fmaf(n0, a0.z, fa[2]); fa[3] = fmaf(n0, a0.w, fa[3]);
                        fa[4] = fmaf(n0, c0v.x, fa[4]); fa[5] = fmaf(n0, c0v.y, fa[5]);
                        fa[6] = fmaf(n0, c0v.z, fa[6]); fa[7] = fmaf(n0, c0v.w, fa[7]);
                        fa[0] = fmaf(n1, a1.x, fa[0]); fa[1] = fmaf(n1, a1.y, fa[1]);
                        fa[2] = fmaf(n1, a1.z, fa[2]); fa[3] = fmaf(n1, a1.w, fa[3]);
                        fa[4] = fmaf(n1, c1v.x, fa[4]); fa[5] = fmaf(n1, c1v.y, fa[5]);
                        fa[6] = fmaf(n1, c1v.z, fa[6]); fa[7] = fmaf(n1, c1v.w, fa[7]);
                        fa[0] = fmaf(n2, a2.x, fa[0]); fa[1] = fmaf(n2, a2.y, fa[1]);
                        fa[2] = fmaf(n2, a2.z, fa[2]); fa[3] = fmaf(n2, a2.w, fa[3]);
                        fa[4] = fmaf(n2, c2v.x, fa[4]); fa[5] = fmaf(n2, c2v.y, fa[5]);
                        fa[6] = fmaf(n2, c2v.z, fa[6]); fa[7] = fmaf(n2, c2v.w, fa[7]);
                        fa[0] = fmaf(n3, a3.x, fa[0]); fa[1] = fmaf(n3, a3.y, fa[1]);
                        fa[2] = fmaf(n3, a3.z, fa[2]); fa[3] = fmaf(n3, a3.w, fa[3]);
                        fa[4] = fmaf(n3, c3v.x, fa[4]); fa[5] = fmaf(n3, c3v.y, fa[5]);
                        fa[6] = fmaf(n3, c3v.z, fa[6]); fa[7] = fmaf(n3, c3v.w, fa[7]);
                    }
                    for (; j < jend; j++) {
                        int rr = __shfl_sync(0xffffffffu, rowm, j);
                        float nm = __shfl_sync(0xffffffffu, edv.y, j);
                        const float4* tp = reinterpret_cast<const float4*>(g_Mtab + rr * D + j0);
                        float4 t0 = tp[0], t1 = tp[1];
                        fa[0] = fmaf(nm, t0.x, fa[0]); fa[1] = fmaf(nm, t0.y, fa[1]);
                        fa[2] = fmaf(nm, t0.z, fa[2]); fa[3] = fmaf(nm, t0.w, fa[3]);
                        fa[4] = fmaf(nm, t1.x, fa[4]); fa[5] = fmaf(nm, t1.y, fa[5]);
                        fa[6] = fmaf(nm, t1.z, fa[6]); fa[7] = fmaf(nm, t1.w, fa[7]);
                    }
                    e = lim;
                }

                // ---- epilogue for row r: combine, store, BN partials ----
                int vrow = v0 + r;
                if (alane && vrow < V) {
                    float v[8];
                    unpack2(acc[r * 4 + 0], v[0], v[1]);
                    unpack2(acc[r * 4 + 1], v[2], v[3]);
                    unpack2(acc[r * 4 + 2], v[4], v[5]);
                    unpack2(acc[r * 4 + 3], v[6], v[7]);
                    #pragma unroll
                    for (int c = 0; c < 8; c++) {
                        v[c] += fa[c] + b0[c];
                        sS[c] += v[c];
                        sQ[c] += v[c] * v[c];
                    }
                    float* op = out + (size_t)vrow * D + j0;
                    *reinterpret_cast<float4*>(op) =
                        make_float4(v[0], v[1], v[2], v[3]);
                    *reinterpret_cast<float4*>(op + 4) =
                        make_float4(v[4], v[5], v[6], v[7]);
                }
            }
        }

        // CTA reduce -> global atomics (dynF reused after all warps finish)
        __syncthreads();
        if (alane) {
            #pragma unroll
            for (int c = 0; c < 8; c++) dynF[team * D + j0 + c] = sS[c];
        }
        __syncthreads();
        if (tid < D) {
            float t = 0.f;
            #pragma unroll
            for (int w = 0; w < 16; w++) t += dynF[w * D + tid];
            atomicAdd(&g_sum[tid], t);
        }
        __syncthreads();
        if (alane) {
            #pragma unroll
            for (int c = 0; c < 8; c++) dynF[team * D + j0 + c] = sQ[c];
        }
        __syncthreads();
        if (tid < D) {
            float t = 0.f;
            #pragma unroll
            for (int w = 0; w < 16; w++) t += dynF[w * D + tid];
            atomicAdd(&g_sumsq[tid], t);
        }
    }
    grid_bar();

    // ---------------- phase 5: BN normalize ----------------
    {
        float invV = 1.f / (float)V;
        if (tid < D) {
            float mean = g_sum[tid] * invV;
            float var = g_sumsq[tid] * invV - mean * mean;
            float sc = bn_w[tid] * rsqrtf(var + 1e-5f);
            rs[tid] = sc;
            fred[tid] = bn_b[tid] - mean * sc;
        }
        __syncthreads();
        int r0 = cta * CHUNK;
        for (int i = tid; i < CHUNK * 50; i += THREADS) {
            int r = r0 + i / 50;
            if (r < V) {
                int c4 = (i % 50) * 4;
                float4* p = reinterpret_cast<float4*>(out + (size_t)r * D + c4);
                float4 v = *p;
                v.x = v.x * rs[c4]     + fred[c4];
                v.y = v.y * rs[c4 + 1] + fred[c4 + 1];
                v.z = v.z * rs[c4 + 2] + fred[c4 + 2];
                v.w = v.w * rs[c4 + 3] + fred[c4 + 3];
                *p = v;
            }
        }
    }
}

// ============================================================================
extern "C" void kernel_launch(void* const* d_in, const int* in_sizes, int n_in,
                              void* d_out, int out_size) {
    const float* x         = (const float*)d_in[0];
    const float* rel_repr  = (const float*)d_in[1];
    const float* edge_norm = (const float*)d_in[2];
    const float* in_w      = (const float*)d_in[3];
    const float* out_w     = (const float*)d_in[4];
    const float* loop_w    = (const float*)d_in[5];
    const float* w_rel     = (const float*)d_in[6];
    const float* loop_rel  = (const float*)d_in[7];
    const float* bias      = (const float*)d_in[8];
    const float* bn_w      = (const float*)d_in[9];
    const float* bn_b      = (const float*)d_in[10];
    const int*   edge_type = (const int*)d_in[11];
    const int*   dst       = (const int*)d_in[12];
    float* out = (float*)d_out;

    int V = in_sizes[0] / D;   // 100000
    int E = in_sizes[2];       // 1000000

    size_t smem = (size_t)(D * D + 4 * D) * sizeof(float);   // 163,200 B
    cudaFuncSetAttribute(mega_kernel,
                         cudaFuncAttributeMaxDynamicSharedMemorySize, (int)smem);

    mega_kernel<<<NCTA, THREADS, smem>>>(x, rel_repr, edge_norm, in_w, out_w,
                                         loop_w, w_rel, loop_rel, bias, bn_w,
                                         bn_b, edge_type, dst, out, V, E);
}